// round 14
// baseline (speedup 1.0000x reference)
#include <cuda_runtime.h>
#include <cuda_bf16.h>
#include <cuda_fp16.h>
#include <cstdint>

#define NB    8
#define SENC  2048
#define SDEC  1024
#define DIN   512
#define UNITS 512

using bf16 = __nv_bfloat16;

// ---------------------------------------------------------------------------
// Scratch (__device__ globals: allocation-free rule)
// ---------------------------------------------------------------------------
__device__ __align__(256) bf16 g_dec_h[(size_t)NB * SDEC * DIN];
__device__ __align__(256) bf16 g_dec_l[(size_t)NB * SDEC * DIN];
__device__ __align__(256) bf16 g_enc_h[(size_t)NB * SENC * DIN];
__device__ __align__(256) bf16 g_enc_l[(size_t)NB * SENC * DIN];
__device__ __align__(256) __half g_enc16[(size_t)NB * SENC * DIN];  // enc fp16
__device__ __align__(256) __half g_wvT16[DIN * UNITS];              // Wv^T fp16
__device__ __align__(256) bf16 g_mt_h[DIN * DIN];      // MT[e][d] = (Wq Wk^T)^T
__device__ __align__(256) bf16 g_mt_l[DIN * DIN];
__device__ __align__(256) bf16 g_t_h[(size_t)NB * SDEC * DIN];   // T = dec*M
__device__ __align__(256) bf16 g_t_l[(size_t)NB * SDEC * DIN];
__device__ __align__(256) __half g_vt16[(size_t)NB * UNITS * SENC]; // V^T fp16
__device__ __align__(256) float g_s[(size_t)NB * SDEC * SENC];      // fp32 scores
__device__ __align__(256) __half g_p16[(size_t)NB * SDEC * SENC];   // P fp16

// ---------------------------------------------------------------------------
// helpers
// ---------------------------------------------------------------------------
__device__ __forceinline__ void split2(float x, bf16& h, bf16& l) {
    h = __float2bfloat16(x);
    l = __float2bfloat16(x - __bfloat162float(h));
}

#define CPA(dst, src) asm volatile( \
    "cp.async.cg.shared.global [%0], [%1], 16;" :: "r"(dst), "l"(src))
#define CP_COMMIT() asm volatile("cp.async.commit_group;")

template <int N>
__device__ __forceinline__ void cp_wait() {
    asm volatile("cp.async.wait_group %0;" :: "n"(N));
}

#define LDSM4(r0,r1,r2,r3,addr) asm volatile( \
    "ldmatrix.sync.aligned.m8n8.x4.shared.b16 {%0,%1,%2,%3}, [%4];" \
    : "=r"(r0),"=r"(r1),"=r"(r2),"=r"(r3) : "r"(addr))

#define MMA_BF16(ac,Af,B0,B1) asm volatile( \
    "mma.sync.aligned.m16n8k16.row.col.f32.bf16.bf16.f32 " \
    "{%0,%1,%2,%3}, {%4,%5,%6,%7}, {%8,%9}, {%0,%1,%2,%3};" \
    : "+f"(ac[0]),"+f"(ac[1]),"+f"(ac[2]),"+f"(ac[3]) \
    : "r"(Af[0]),"r"(Af[1]),"r"(Af[2]),"r"(Af[3]), "r"(B0),"r"(B1))

#define MMA_FP16(ac,Af,B0,B1) asm volatile( \
    "mma.sync.aligned.m16n8k16.row.col.f32.f16.f16.f32 " \
    "{%0,%1,%2,%3}, {%4,%5,%6,%7}, {%8,%9}, {%0,%1,%2,%3};" \
    : "+f"(ac[0]),"+f"(ac[1]),"+f"(ac[2]),"+f"(ac[3]) \
    : "r"(Af[0]),"r"(Af[1]),"r"(Af[2]),"r"(Af[3]), "r"(B0),"r"(B1))

// XOR-swizzled smem offset for a (row, 16B-chunk) of a 64B-wide tile.
__device__ __forceinline__ uint32_t swz(int row, int c) {
    return (uint32_t)(row * 64 + ((c ^ ((row >> 1) & 3)) << 4));
}

// ---------------------------------------------------------------------------
// 4-warp NT GEMM mainloop (R9 configuration — single-buffered fragments).
// BM=64, BN=128, BK=32; warps as 1x4 (warp tile 64x32). TERMS=3: bf16 hi/lo
// split (3 MMA terms). TERMS=1 & FP16: plain fp16. XOR-swizzled unpadded
// smem. Single-sync software pipeline. acc[4][4][4] fp32.
// ---------------------------------------------------------------------------
template <int TERMS, bool FP16, int NSTG>
__device__ __forceinline__ void gemm_mainloop(
    const uint16_t* __restrict__ Ah, const uint16_t* __restrict__ Al,
    const uint16_t* __restrict__ Bh, const uint16_t* __restrict__ Bl,
    long long aBase, long long bBase, int K,
    float acc[4][4][4], char* smem)
{
    constexpr int A_TB = 64 * 64;       // 4096 B
    constexpr int B_TB = 128 * 64;      // 8192 B
    constexpr int BOFF = (TERMS == 3) ? 2 * A_TB : A_TB;
    constexpr int STG  = (TERMS == 3) ? 2 * (A_TB + B_TB) : (A_TB + B_TB);

    const int tid  = threadIdx.x;
    const int wid  = tid >> 5;
    const int lane = tid & 31;
    const int wn = wid * 32;

    const uint32_t sm0 = (uint32_t)__cvta_generic_to_shared(smem);

    const int a_row = (lane & 7) + ((lane >> 3) & 1) * 8;
    const int a_kc  = ((lane >> 4) & 1);        // k-chunk (16B) within k16
    const int b_row = (lane & 7) + ((lane >> 4) & 1) * 8;
    const int b_kc  = ((lane >> 3) & 1);

    const int nk = K / 32;

    auto load_stage = [&](int s, int k0) {
        const uint32_t st = sm0 + s * STG;
        #pragma unroll
        for (int c = tid; c < 256; c += 128) {        // A: 64 rows x 4 chunks
            const int row = c >> 2, ch = c & 3;
            const uint32_t sa = st + swz(row, ch);
            const long long g = aBase + (long long)row * K + k0 + ch * 8;
            CPA(sa, Ah + g);
            if (TERMS == 3) CPA(sa + A_TB, Al + g);
        }
        #pragma unroll
        for (int c = tid; c < 512; c += 128) {        // B: 128 rows x 4 chunks
            const int row = c >> 2, ch = c & 3;
            const uint32_t sb = st + BOFF + swz(row, ch);
            const long long g = bBase + (long long)row * K + k0 + ch * 8;
            CPA(sb, Bh + g);
            if (TERMS == 3) CPA(sb + B_TB, Bl + g);
        }
    };

    #pragma unroll
    for (int s = 0; s < NSTG - 1; s++) {
        load_stage(s, s * 32);
        CP_COMMIT();
    }

    for (int kt = 0; kt < nk; kt++) {
        cp_wait<NSTG - 2>();
        __syncthreads();

        const int knext = kt + NSTG - 1;
        if (knext < nk)
            load_stage(knext % NSTG, knext * 32);     // overlaps compute
        CP_COMMIT();

        const uint32_t st  = sm0 + (kt % NSTG) * STG;
        const uint32_t stA = st, stB = st + BOFF;

        #pragma unroll
        for (int ks = 0; ks < 2; ks++) {
            const int kc = ks * 2;                    // 16B chunk base of k16
            uint32_t ah[4][4], al[4][4];
            #pragma unroll
            for (int i = 0; i < 4; i++) {
                const int row = i * 16 + a_row;
                const uint32_t off = swz(row, kc + a_kc);
                LDSM4(ah[i][0], ah[i][1], ah[i][2], ah[i][3], stA + off);
                if (TERMS == 3)
                    LDSM4(al[i][0], al[i][1], al[i][2], al[i][3], stA + A_TB + off);
            }
            #pragma unroll
            for (int j2 = 0; j2 < 2; j2++) {
                uint32_t bh[4], bl[4];
                const int row = wn + j2 * 16 + b_row;
                const uint32_t off = swz(row, kc + b_kc);
                LDSM4(bh[0], bh[1], bh[2], bh[3], stB + off);
                if (TERMS == 3)
                    LDSM4(bl[0], bl[1], bl[2], bl[3], stB + B_TB + off);
                #pragma unroll
                for (int i = 0; i < 4; i++) {
                    if (FP16) {
                        MMA_FP16(acc[i][2*j2],   ah[i], bh[0], bh[1]);
                        MMA_FP16(acc[i][2*j2+1], ah[i], bh[2], bh[3]);
                    } else {
                        MMA_BF16(acc[i][2*j2],   ah[i], bh[0], bh[1]);
                        MMA_BF16(acc[i][2*j2+1], ah[i], bh[2], bh[3]);
                        if (TERMS == 3) {
                            MMA_BF16(acc[i][2*j2],   ah[i], bl[0], bl[1]);
                            MMA_BF16(acc[i][2*j2],   al[i], bh[0], bh[1]);
                            MMA_BF16(acc[i][2*j2+1], ah[i], bl[2], bl[3]);
                            MMA_BF16(acc[i][2*j2+1], al[i], bh[2], bh[3]);
                        }
                    }
                }
            }
        }
    }
}

constexpr int SMEM_G3 = 2 * 2 * (64 * 64 + 128 * 64);   // 49152 (TERMS=3, NST=2)
constexpr int SMEM_F1 = 4 * (64 * 64 + 128 * 64);       // 49152 (fp16, NST=4)

// ---------------------------------------------------------------------------
// T projection: T = dec @ M (TERMS=3), split-bf16 epilogue.
// BM=64, BN=128, K=512. grid (4, 128)
// ---------------------------------------------------------------------------
__global__ void __launch_bounds__(128, 4)
tproj_kernel(const bf16* dec_h, const bf16* dec_l,
             const bf16* mt_h, const bf16* mt_l,
             bf16* t_h, bf16* t_l)
{
    extern __shared__ __align__(128) char smem[];
    const int n0 = blockIdx.x * 128;
    const int arow0 = blockIdx.y * 64;

    float acc[4][4][4];
    #pragma unroll
    for (int i = 0; i < 4; i++)
        #pragma unroll
        for (int j = 0; j < 4; j++)
            #pragma unroll
            for (int e = 0; e < 4; e++) acc[i][j][e] = 0.f;

    gemm_mainloop<3, false, 2>(
        (const uint16_t*)dec_h, (const uint16_t*)dec_l,
        (const uint16_t*)mt_h, (const uint16_t*)mt_l,
        (long long)arow0 * DIN, (long long)n0 * DIN, DIN, acc, smem);

    const int wid = threadIdx.x >> 5, lane = threadIdx.x & 31;
    const int rr0 = arow0 + (lane >> 2);
    const int cc0 = n0 + wid * 32 + (lane & 3) * 2;

    #pragma unroll
    for (int i = 0; i < 4; i++) {
        #pragma unroll
        for (int j = 0; j < 4; j++) {
            const float* a = acc[i][j];
            const int r0 = rr0 + i * 16;
            const int c  = cc0 + j * 8;
            bf16 h0,l0,h1,l1,h2,l2,h3,l3;
            split2(a[0],h0,l0); split2(a[1],h1,l1);
            split2(a[2],h2,l2); split2(a[3],h3,l3);
            const size_t i0 = (size_t)r0 * DIN + c;
            const size_t i1 = (size_t)(r0 + 8) * DIN + c;
            *(__nv_bfloat162*)(t_h + i0) = __nv_bfloat162(h0, h1);
            *(__nv_bfloat162*)(t_l + i0) = __nv_bfloat162(l0, l1);
            *(__nv_bfloat162*)(t_h + i1) = __nv_bfloat162(h2, h3);
            *(__nv_bfloat162*)(t_l + i1) = __nv_bfloat162(l2, l3);
        }
    }
}

// ---------------------------------------------------------------------------
// V projection (fp16 single-term): V^T = (enc16 @ WvT16^T)^T per batch.
// BM=64, BN=128, K=512, NSTG=4. grid (4, 256)
// ---------------------------------------------------------------------------
__global__ void __launch_bounds__(128, 4)
vproj_kernel(const __half* enc16, const __half* wvT16, __half* vt)
{
    extern __shared__ __align__(128) char smem[];
    const int n0 = blockIdx.x * 128;
    const int arow0 = blockIdx.y * 64;

    float acc[4][4][4];
    #pragma unroll
    for (int i = 0; i < 4; i++)
        #pragma unroll
        for (int j = 0; j < 4; j++)
            #pragma unroll
            for (int e = 0; e < 4; e++) acc[i][j][e] = 0.f;

    gemm_mainloop<1, true, 4>(
        (const uint16_t*)enc16, nullptr,
        (const uint16_t*)wvT16, nullptr,
        (long long)arow0 * DIN, (long long)n0 * DIN, DIN, acc, smem);

    const int wid = threadIdx.x >> 5, lane = threadIdx.x & 31;
    const int rr0 = arow0 + (lane >> 2);
    const int cc0 = n0 + wid * 32 + (lane & 3) * 2;

    #pragma unroll
    for (int i = 0; i < 4; i++) {
        #pragma unroll
        for (int j = 0; j < 4; j++) {
            const float* a = acc[i][j];
            const int r0 = rr0 + i * 16;
            const int c  = cc0 + j * 8;
            #pragma unroll
            for (int e = 0; e < 4; e++) {
                const int rr = r0 + (e >> 1) * 8;        // enc row
                const int cn = c + (e & 1);              // unit
                const size_t idx = (size_t)(rr >> 11) * ((size_t)UNITS * SENC)
                                 + (size_t)cn * SENC + (rr & 2047);
                vt[idx] = __float2half(a[e]);
            }
        }
    }
}

// ---------------------------------------------------------------------------
// Scores: S[b] = T[b] @ enc[b]^T, BM=64, BN=128, K=512, TERMS=3, fp32 out.
// grid = (16, 16, 8)
// ---------------------------------------------------------------------------
__global__ void __launch_bounds__(128, 4)
scores_kernel(const bf16* t_h, const bf16* t_l,
              const bf16* enc_h, const bf16* enc_l, float* __restrict__ S)
{
    extern __shared__ __align__(128) char smem[];
    const int z = blockIdx.z;
    const int m0 = blockIdx.y * 64;
    const int n0 = blockIdx.x * 128;

    float acc[4][4][4];
    #pragma unroll
    for (int i = 0; i < 4; i++)
        #pragma unroll
        for (int j = 0; j < 4; j++)
            #pragma unroll
            for (int e = 0; e < 4; e++) acc[i][j][e] = 0.f;

    gemm_mainloop<3, false, 2>(
        (const uint16_t*)t_h, (const uint16_t*)t_l,
        (const uint16_t*)enc_h, (const uint16_t*)enc_l,
        ((long long)z * SDEC + m0) * DIN,
        ((long long)z * SENC + n0) * DIN, DIN, acc, smem);

    const int wid = threadIdx.x >> 5, lane = threadIdx.x & 31;
    const int rr0 = m0 + (lane >> 2);
    const int cc0 = n0 + wid * 32 + (lane & 3) * 2;
    float* Sb = S + (long long)z * SDEC * SENC;

    #pragma unroll
    for (int i = 0; i < 4; i++) {
        #pragma unroll
        for (int j = 0; j < 4; j++) {
            const float* a = acc[i][j];
            const int r0 = rr0 + i * 16;
            const int c  = cc0 + j * 8;
            *(float2*)(Sb + (long long)r0 * SENC + c)       = make_float2(a[0], a[1]);
            *(float2*)(Sb + (long long)(r0 + 8) * SENC + c) = make_float2(a[2], a[3]);
        }
    }
}

// ---------------------------------------------------------------------------
// PV: out[b] = P[b] @ V[b]. BM=64, BN=128, K=2048, fp16, NSTG=4. grid (4,16,8)
// ---------------------------------------------------------------------------
__global__ void __launch_bounds__(128, 4)
pv_kernel(const __half* P, const __half* VT, float* __restrict__ O)
{
    extern __shared__ __align__(128) char smem[];
    const int z = blockIdx.z;
    const int m0 = blockIdx.y * 64;
    const int n0 = blockIdx.x * 128;

    float acc[4][4][4];
    #pragma unroll
    for (int i = 0; i < 4; i++)
        #pragma unroll
        for (int j = 0; j < 4; j++)
            #pragma unroll
            for (int e = 0; e < 4; e++) acc[i][j][e] = 0.f;

    gemm_mainloop<1, true, 4>(
        (const uint16_t*)P, nullptr, (const uint16_t*)VT, nullptr,
        ((long long)z * SDEC + m0) * SENC,
        ((long long)z * UNITS + n0) * SENC, SENC, acc, smem);

    const int wid = threadIdx.x >> 5, lane = threadIdx.x & 31;
    const int rr0 = m0 + (lane >> 2);
    const int cc0 = n0 + wid * 32 + (lane & 3) * 2;
    float* Ob = O + (long long)z * SDEC * UNITS;

    #pragma unroll
    for (int i = 0; i < 4; i++) {
        #pragma unroll
        for (int j = 0; j < 4; j++) {
            const float* a = acc[i][j];
            const int r0 = rr0 + i * 16;
            const int c  = cc0 + j * 8;
            *(float2*)(Ob + (long long)r0 * UNITS + c)       = make_float2(a[0], a[1]);
            *(float2*)(Ob + (long long)(r0 + 8) * UNITS + c) = make_float2(a[2], a[3]);
        }
    }
}

// ---------------------------------------------------------------------------
// Merged prep kernel (256 threads):
//  blocks [0,1024):    dec -> bf16 hi/lo           (4x ILP)
//  blocks [1024,3072): enc -> bf16 hi/lo + fp16    (4x ILP)
//  blocks [3072,3328): Wv  -> Wv^T fp16            (4x ILP)
//  blocks [3328,3584): MT = Wk*Wq^T (fp32 exact) -> split bf16 (32x32 tile)
// ---------------------------------------------------------------------------
__global__ void __launch_bounds__(256)
prep_kernel(const float4* __restrict__ dec, const float4* __restrict__ enc,
            const float* __restrict__ Wv,
            const float* __restrict__ Wk, const float* __restrict__ Wq,
            __nv_bfloat162* __restrict__ dh, __nv_bfloat162* __restrict__ dl,
            __nv_bfloat162* __restrict__ eh, __nv_bfloat162* __restrict__ el,
            __half2* __restrict__ e16, __half* __restrict__ v16,
            bf16* __restrict__ mh, bf16* __restrict__ ml)
{
    const int b = blockIdx.x;
    if (b < 1024) {
        const int base = b * 1024;
        float4 v[4];
        #pragma unroll
        for (int it = 0; it < 4; it++)
            v[it] = dec[base + it * 256 + threadIdx.x];
        #pragma unroll
        for (int it = 0; it < 4; it++) {
            const int i = base + it * 256 + threadIdx.x;
            bf16 h0,l0,h1,l1,h2,l2,h3,l3;
            split2(v[it].x,h0,l0); split2(v[it].y,h1,l1);
            split2(v[it].z,h2,l2); split2(v[it].w,h3,l3);
            dh[2*i]   = __nv_bfloat162(h0,h1);
            dh[2*i+1] = __nv_bfloat162(h2,h3);
            dl[2*i]   = __nv_bfloat162(l0,l1);
            dl[2*i+1] = __nv_bfloat162(l2,l3);
        }
    } else if (b < 3072) {
        const int base = (b - 1024) * 1024;
        float4 v[4];
        #pragma unroll
        for (int it = 0; it < 4; it++)
            v[it] = enc[base + it * 256 + threadIdx.x];
        #pragma unroll
        for (int it = 0; it < 4; it++) {
            const int i = base + it * 256 + threadIdx.x;
            bf16 h0,l0,h1,l1,h2,l2,h3,l3;
            split2(v[it].x,h0,l0); split2(v[it].y,h1,l1);
            split2(v[it].z,h2,l2); split2(v[it].w,h3,l3);
            eh[2*i]   = __nv_bfloat162(h0,h1);
            eh[2*i+1] = __nv_bfloat162(h2,h3);
            el[2*i]   = __nv_bfloat162(l0,l1);
            el[2*i+1] = __nv_bfloat162(l2,l3);
            e16[2*i]   = __floats2half2_rn(v[it].x, v[it].y);
            e16[2*i+1] = __floats2half2_rn(v[it].z, v[it].w);
        }
    } else if (b < 3328) {
        const int base = (b - 3072) * 1024;               // [0, 262144)
        float w[4];
        #pragma unroll
        for (int it = 0; it < 4; it++)
            w[it] = Wv[base + it * 256 + threadIdx.x];
        #pragma unroll
        for (int it = 0; it < 4; it++) {
            const int idx = base + it * 256 + threadIdx.x;
            const int k = idx >> 9, n = idx & 511;
            v16[n * 512 + k] = __float2half(w[it]);
        }
    } else {
        // ---- MT = Wk * Wq^T (exact fp32 SIMT) ----
        __shared__ float As[16][36];
        __shared__ float Bs[16][36];
        const int mb = b - 3328;                          // 0..255
        const int e0 = (mb >> 4) * 32, d0 = (mb & 15) * 32;
        const int tid = threadIdx.x;
        const int ty = tid >> 4, tx = tid & 15;

        float c00 = 0.f, c01 = 0.f, c10 = 0.f, c11 = 0.f;

        for (int u0 = 0; u0 < 512; u0 += 16) {
            {
                const int t = tid & 127;
                const int row = t >> 2, col = (t & 3) * 4;
                if (tid < 128) {
                    float4 a = *(const float4*)(Wk + (size_t)(e0 + row) * 512 + u0 + col);
                    As[col+0][row] = a.x; As[col+1][row] = a.y;
                    As[col+2][row] = a.z; As[col+3][row] = a.w;
                } else {
                    float4 bb = *(const float4*)(Wq + (size_t)(d0 + row) * 512 + u0 + col);
                    Bs[col+0][row] = bb.x; Bs[col+1][row] = bb.y;
                    Bs[col+2][row] = bb.z; Bs[col+3][row] = bb.w;
                }
            }
            __syncthreads();
            #pragma unroll
            for (int k = 0; k < 16; k++) {
                float a0 = As[k][ty*2], a1 = As[k][ty*2+1];
                float b0 = Bs[k][tx*2], b1 = Bs[k][tx*2+1];
                c00 += a0*b0; c01 += a0*b1; c10 += a1*b0; c11 += a1*b1;
            }
            __syncthreads();
        }
        bf16 h, l;
        size_t i0 = (size_t)(e0 + ty*2) * 512 + d0 + tx*2;
        size_t i1 = i0 + 512;
        split2(c00, h, l); mh[i0]   = h; ml[i0]   = l;
        split2(c01, h, l); mh[i0+1] = h; ml[i0+1] = l;
        split2(c10, h, l); mh[i1]   = h; ml[i1]   = l;
        split2(c11, h, l); mh[i1+1] = h; ml[i1+1] = l;
    }
}

// ---------------------------------------------------------------------------
// Row softmax over 2048 fp32 scores -> fp16 probabilities
// ---------------------------------------------------------------------------
__inline__ __device__ float warpMax(float v) {
    #pragma unroll
    for (int o = 16; o; o >>= 1) v = fmaxf(v, __shfl_xor_sync(0xffffffffu, v, o));
    return v;
}
__inline__ __device__ float warpSum(float v) {
    #pragma unroll
    for (int o = 16; o; o >>= 1) v += __shfl_xor_sync(0xffffffffu, v, o);
    return v;
}

__global__ void __launch_bounds__(256)
softmax_h(const float* __restrict__ S, __half* __restrict__ P)
{
    const long long row = blockIdx.x;
    const float4* p = (const float4*)(S + row * (long long)SENC);
    const int tid = threadIdx.x, lane = tid & 31, wid = tid >> 5;

    float4 v0 = p[tid];
    float4 v1 = p[tid + 256];

    float m = fmaxf(fmaxf(fmaxf(v0.x, v0.y), fmaxf(v0.z, v0.w)),
                    fmaxf(fmaxf(v1.x, v1.y), fmaxf(v1.z, v1.w)));
    __shared__ float smax[8], ssum[8];
    m = warpMax(m);
    if (lane == 0) smax[wid] = m;
    __syncthreads();
    float bm = smax[0];
    #pragma unroll
    for (int i = 1; i < 8; i++) bm = fmaxf(bm, smax[i]);

    v0.x = __expf(v0.x - bm); v0.y = __expf(v0.y - bm);
    v0.z = __expf(v0.z - bm); v0.w = __expf(v0.w - bm);
    v1.x = __expf(v1.x - bm); v1.y = __expf(v1.y - bm);
    v1.z = __expf(v1.z - bm); v1.w = __expf(v1.w - bm);

    float s = (v0.x + v0.y + v0.z + v0.w) + (v1.x + v1.y + v1.z + v1.w);
    s = warpSum(s);
    if (lane == 0) ssum[wid] = s;
    __syncthreads();
    float bs = 0.f;
    #pragma unroll
    for (int i = 0; i < 8; i++) bs += ssum[i];
    const float inv = 1.0f / bs;

    __half2* ph = (__half2*)(P + row * (long long)SENC);
    ph[2*tid]         = __floats2half2_rn(v0.x * inv, v0.y * inv);
    ph[2*tid+1]       = __floats2half2_rn(v0.z * inv, v0.w * inv);
    ph[512 + 2*tid]   = __floats2half2_rn(v1.x * inv, v1.y * inv);
    ph[512 + 2*tid+1] = __floats2half2_rn(v1.z * inv, v1.w * inv);
}

// ---------------------------------------------------------------------------
extern "C" void kernel_launch(void* const* d_in, const int* in_sizes, int n_in,
                              void* d_out, int out_size)
{
    const float* enc = (const float*)d_in[0];
    const float* dec = (const float*)d_in[1];
    const float* Wq  = (const float*)d_in[2];
    const float* Wk  = (const float*)d_in[3];
    const float* Wv  = (const float*)d_in[4];
    float* out = (float*)d_out;

    bf16 *dec_h,*dec_l,*enc_h,*enc_l,*mt_h,*mt_l,*t_h,*t_l;
    __half *enc16, *wvT16, *vt16, *p16;
    float *s;
    cudaGetSymbolAddress((void**)&dec_h, g_dec_h);
    cudaGetSymbolAddress((void**)&dec_l, g_dec_l);
    cudaGetSymbolAddress((void**)&enc_h, g_enc_h);
    cudaGetSymbolAddress((void**)&enc_l, g_enc_l);
    cudaGetSymbolAddress((void**)&enc16, g_enc16);
    cudaGetSymbolAddress((void**)&wvT16, g_wvT16);
    cudaGetSymbolAddress((void**)&mt_h, g_mt_h);
    cudaGetSymbolAddress((void**)&mt_l, g_mt_l);
    cudaGetSymbolAddress((void**)&t_h, g_t_h);
    cudaGetSymbolAddress((void**)&t_l, g_t_l);
    cudaGetSymbolAddress((void**)&vt16, g_vt16);
    cudaGetSymbolAddress((void**)&p16, g_p16);
    cudaGetSymbolAddress((void**)&s, g_s);

    cudaFuncSetAttribute(tproj_kernel,  cudaFuncAttributeMaxDynamicSharedMemorySize, SMEM_G3);
    cudaFuncSetAttribute(vproj_kernel,  cudaFuncAttributeMaxDynamicSharedMemorySize, SMEM_F1);
    cudaFuncSetAttribute(scores_kernel, cudaFuncAttributeMaxDynamicSharedMemorySize, SMEM_G3);
    cudaFuncSetAttribute(pv_kernel,     cudaFuncAttributeMaxDynamicSharedMemorySize, SMEM_F1);

    // 1. all prep: splits + MT = Wk*Wq^T, one launch
    prep_kernel<<<3584, 256>>>(
        (const float4*)dec, (const float4*)enc, Wv, Wk, Wq,
        (__nv_bfloat162*)dec_h, (__nv_bfloat162*)dec_l,
        (__nv_bfloat162*)enc_h, (__nv_bfloat162*)enc_l,
        (__half2*)enc16, wvT16, mt_h, mt_l);

    // 2. V^T projection (fp16 single-term)
    vproj_kernel<<<dim3(4, 256), 128, SMEM_F1>>>(enc16, wvT16, vt16);

    // 3. T = dec * M (3-term bf16)
    tproj_kernel<<<dim3(4, 128), 128, SMEM_G3>>>(dec_h, dec_l, mt_h, mt_l, t_h, t_l);

    // 4. scores S = T @ enc^T (batched)
    scores_kernel<<<dim3(16, 16, 8), 128, SMEM_G3>>>(t_h, t_l, enc_h, enc_l, s);

    // 5. softmax -> fp16 P
    softmax_h<<<NB * SDEC, 256>>>(s, p16);

    // 6. out = P @ V
    pv_kernel<<<dim3(4, 16, 8), 128, SMEM_F1>>>(p16, vt16, out);
}

// round 15
// speedup vs baseline: 1.0417x; 1.0417x over previous
#include <cuda_runtime.h>
#include <cuda_bf16.h>
#include <cuda_fp16.h>
#include <cstdint>

#define NB    8
#define SENC  2048
#define SDEC  1024
#define DIN   512
#define UNITS 512

using bf16 = __nv_bfloat16;

// ---------------------------------------------------------------------------
// Scratch (__device__ globals: allocation-free rule)
// ---------------------------------------------------------------------------
__device__ __align__(256) bf16 g_dec_h[(size_t)NB * SDEC * DIN];
__device__ __align__(256) bf16 g_dec_l[(size_t)NB * SDEC * DIN];
__device__ __align__(256) bf16 g_enc_h[(size_t)NB * SENC * DIN];
__device__ __align__(256) bf16 g_enc_l[(size_t)NB * SENC * DIN];
__device__ __align__(256) __half g_enc16[(size_t)NB * SENC * DIN];  // enc fp16
__device__ __align__(256) __half g_wvT16[DIN * UNITS];              // Wv^T fp16
__device__ __align__(256) bf16 g_mt_h[DIN * DIN];      // MT[e][d] = (Wq Wk^T)^T
__device__ __align__(256) bf16 g_mt_l[DIN * DIN];
__device__ __align__(256) bf16 g_t_h[(size_t)NB * SDEC * DIN];   // T = dec*M
__device__ __align__(256) bf16 g_t_l[(size_t)NB * SDEC * DIN];
__device__ __align__(256) __half g_vt16[(size_t)NB * UNITS * SENC]; // V^T fp16
__device__ __align__(256) float g_s[(size_t)NB * SDEC * SENC];      // fp32 scores
__device__ __align__(256) __half g_p16[(size_t)NB * SDEC * SENC];   // P fp16

// ---------------------------------------------------------------------------
// helpers
// ---------------------------------------------------------------------------
__device__ __forceinline__ void split2(float x, bf16& h, bf16& l) {
    h = __float2bfloat16(x);
    l = __float2bfloat16(x - __bfloat162float(h));
}

#define CPA(dst, src) asm volatile( \
    "cp.async.cg.shared.global [%0], [%1], 16;" :: "r"(dst), "l"(src))
#define CP_COMMIT() asm volatile("cp.async.commit_group;")

template <int N>
__device__ __forceinline__ void cp_wait() {
    asm volatile("cp.async.wait_group %0;" :: "n"(N));
}

#define LDSM4(r0,r1,r2,r3,addr) asm volatile( \
    "ldmatrix.sync.aligned.m8n8.x4.shared.b16 {%0,%1,%2,%3}, [%4];" \
    : "=r"(r0),"=r"(r1),"=r"(r2),"=r"(r3) : "r"(addr))

#define MMA_BF16(ac,Af,B0,B1) asm volatile( \
    "mma.sync.aligned.m16n8k16.row.col.f32.bf16.bf16.f32 " \
    "{%0,%1,%2,%3}, {%4,%5,%6,%7}, {%8,%9}, {%0,%1,%2,%3};" \
    : "+f"(ac[0]),"+f"(ac[1]),"+f"(ac[2]),"+f"(ac[3]) \
    : "r"(Af[0]),"r"(Af[1]),"r"(Af[2]),"r"(Af[3]), "r"(B0),"r"(B1))

#define MMA_FP16(ac,Af,B0,B1) asm volatile( \
    "mma.sync.aligned.m16n8k16.row.col.f32.f16.f16.f32 " \
    "{%0,%1,%2,%3}, {%4,%5,%6,%7}, {%8,%9}, {%0,%1,%2,%3};" \
    : "+f"(ac[0]),"+f"(ac[1]),"+f"(ac[2]),"+f"(ac[3]) \
    : "r"(Af[0]),"r"(Af[1]),"r"(Af[2]),"r"(Af[3]), "r"(B0),"r"(B1))

// XOR-swizzled smem offset for a (row, 16B-chunk) of a 64B-wide tile.
__device__ __forceinline__ uint32_t swz(int row, int c) {
    return (uint32_t)(row * 64 + ((c ^ ((row >> 1) & 3)) << 4));
}

// ---------------------------------------------------------------------------
// 4-warp NT GEMM mainloop (R9 configuration — single-buffered fragments).
// BM=64, BN=128, BK=32; warps as 1x4 (warp tile 64x32). TERMS=3: bf16 hi/lo
// split (3 MMA terms). TERMS=1 & FP16: plain fp16. XOR-swizzled unpadded
// smem. Single-sync software pipeline. acc[4][4][4] fp32.
// ---------------------------------------------------------------------------
template <int TERMS, bool FP16, int NSTG>
__device__ __forceinline__ void gemm_mainloop(
    const uint16_t* __restrict__ Ah, const uint16_t* __restrict__ Al,
    const uint16_t* __restrict__ Bh, const uint16_t* __restrict__ Bl,
    long long aBase, long long bBase, int K,
    float acc[4][4][4], char* smem)
{
    constexpr int A_TB = 64 * 64;       // 4096 B
    constexpr int B_TB = 128 * 64;      // 8192 B
    constexpr int BOFF = (TERMS == 3) ? 2 * A_TB : A_TB;
    constexpr int STG  = (TERMS == 3) ? 2 * (A_TB + B_TB) : (A_TB + B_TB);

    const int tid  = threadIdx.x;
    const int wid  = tid >> 5;
    const int lane = tid & 31;
    const int wn = wid * 32;

    const uint32_t sm0 = (uint32_t)__cvta_generic_to_shared(smem);

    const int a_row = (lane & 7) + ((lane >> 3) & 1) * 8;
    const int a_kc  = ((lane >> 4) & 1);        // k-chunk (16B) within k16
    const int b_row = (lane & 7) + ((lane >> 4) & 1) * 8;
    const int b_kc  = ((lane >> 3) & 1);

    const int nk = K / 32;

    auto load_stage = [&](int s, int k0) {
        const uint32_t st = sm0 + s * STG;
        #pragma unroll
        for (int c = tid; c < 256; c += 128) {        // A: 64 rows x 4 chunks
            const int row = c >> 2, ch = c & 3;
            const uint32_t sa = st + swz(row, ch);
            const long long g = aBase + (long long)row * K + k0 + ch * 8;
            CPA(sa, Ah + g);
            if (TERMS == 3) CPA(sa + A_TB, Al + g);
        }
        #pragma unroll
        for (int c = tid; c < 512; c += 128) {        // B: 128 rows x 4 chunks
            const int row = c >> 2, ch = c & 3;
            const uint32_t sb = st + BOFF + swz(row, ch);
            const long long g = bBase + (long long)row * K + k0 + ch * 8;
            CPA(sb, Bh + g);
            if (TERMS == 3) CPA(sb + B_TB, Bl + g);
        }
    };

    #pragma unroll
    for (int s = 0; s < NSTG - 1; s++) {
        load_stage(s, s * 32);
        CP_COMMIT();
    }

    for (int kt = 0; kt < nk; kt++) {
        cp_wait<NSTG - 2>();
        __syncthreads();

        const int knext = kt + NSTG - 1;
        if (knext < nk)
            load_stage(knext % NSTG, knext * 32);     // overlaps compute
        CP_COMMIT();

        const uint32_t st  = sm0 + (kt % NSTG) * STG;
        const uint32_t stA = st, stB = st + BOFF;

        #pragma unroll
        for (int ks = 0; ks < 2; ks++) {
            const int kc = ks * 2;                    // 16B chunk base of k16
            uint32_t ah[4][4], al[4][4];
            #pragma unroll
            for (int i = 0; i < 4; i++) {
                const int row = i * 16 + a_row;
                const uint32_t off = swz(row, kc + a_kc);
                LDSM4(ah[i][0], ah[i][1], ah[i][2], ah[i][3], stA + off);
                if (TERMS == 3)
                    LDSM4(al[i][0], al[i][1], al[i][2], al[i][3], stA + A_TB + off);
            }
            #pragma unroll
            for (int j2 = 0; j2 < 2; j2++) {
                uint32_t bh[4], bl[4];
                const int row = wn + j2 * 16 + b_row;
                const uint32_t off = swz(row, kc + b_kc);
                LDSM4(bh[0], bh[1], bh[2], bh[3], stB + off);
                if (TERMS == 3)
                    LDSM4(bl[0], bl[1], bl[2], bl[3], stB + B_TB + off);
                #pragma unroll
                for (int i = 0; i < 4; i++) {
                    if (FP16) {
                        MMA_FP16(acc[i][2*j2],   ah[i], bh[0], bh[1]);
                        MMA_FP16(acc[i][2*j2+1], ah[i], bh[2], bh[3]);
                    } else {
                        MMA_BF16(acc[i][2*j2],   ah[i], bh[0], bh[1]);
                        MMA_BF16(acc[i][2*j2+1], ah[i], bh[2], bh[3]);
                        if (TERMS == 3) {
                            MMA_BF16(acc[i][2*j2],   ah[i], bl[0], bl[1]);
                            MMA_BF16(acc[i][2*j2],   al[i], bh[0], bh[1]);
                            MMA_BF16(acc[i][2*j2+1], ah[i], bl[2], bl[3]);
                            MMA_BF16(acc[i][2*j2+1], al[i], bh[2], bh[3]);
                        }
                    }
                }
            }
        }
    }
}

constexpr int SMEM_G3 = 2 * 2 * (64 * 64 + 128 * 64);   // 49152 (TERMS=3, NST=2)
constexpr int SMEM_F1 = 4 * (64 * 64 + 128 * 64);       // 49152 (fp16, NST=4)

// ---------------------------------------------------------------------------
// Merged projection kernel: grid (4, 384).
//   y < 256 : V^T = enc16 @ WvT16^T (fp16 single-term, NSTG=4)
//   y >= 256: T = dec @ M (TERMS=3 bf16, NSTG=2), split-bf16 epilogue
// ---------------------------------------------------------------------------
__global__ void __launch_bounds__(128, 4)
proj2_kernel(const bf16* dec_h, const bf16* dec_l,
             const bf16* mt_h, const bf16* mt_l,
             const __half* enc16, const __half* wvT16,
             bf16* t_h, bf16* t_l, __half* vt)
{
    extern __shared__ __align__(128) char smem[];
    const int y = blockIdx.y;
    const int n0 = blockIdx.x * 128;
    const int wid = threadIdx.x >> 5, lane = threadIdx.x & 31;

    float acc[4][4][4];
    #pragma unroll
    for (int i = 0; i < 4; i++)
        #pragma unroll
        for (int j = 0; j < 4; j++)
            #pragma unroll
            for (int e = 0; e < 4; e++) acc[i][j][e] = 0.f;

    if (y < 256) {
        // ---- V projection (fp16 single-term) ----
        const int arow0 = y * 64;
        gemm_mainloop<1, true, 4>(
            (const uint16_t*)enc16, nullptr,
            (const uint16_t*)wvT16, nullptr,
            (long long)arow0 * DIN, (long long)n0 * DIN, DIN, acc, smem);

        const int rr0 = arow0 + (lane >> 2);
        const int cc0 = n0 + wid * 32 + (lane & 3) * 2;
        #pragma unroll
        for (int i = 0; i < 4; i++) {
            #pragma unroll
            for (int j = 0; j < 4; j++) {
                const float* a = acc[i][j];
                const int r0 = rr0 + i * 16;
                const int c  = cc0 + j * 8;
                #pragma unroll
                for (int e = 0; e < 4; e++) {
                    const int rr = r0 + (e >> 1) * 8;        // enc row
                    const int cn = c + (e & 1);              // unit
                    const size_t idx = (size_t)(rr >> 11) * ((size_t)UNITS * SENC)
                                     + (size_t)cn * SENC + (rr & 2047);
                    vt[idx] = __float2half(a[e]);
                }
            }
        }
    } else {
        // ---- T projection (3-term bf16) ----
        const int arow0 = (y - 256) * 64;
        gemm_mainloop<3, false, 2>(
            (const uint16_t*)dec_h, (const uint16_t*)dec_l,
            (const uint16_t*)mt_h, (const uint16_t*)mt_l,
            (long long)arow0 * DIN, (long long)n0 * DIN, DIN, acc, smem);

        const int rr0 = arow0 + (lane >> 2);
        const int cc0 = n0 + wid * 32 + (lane & 3) * 2;
        #pragma unroll
        for (int i = 0; i < 4; i++) {
            #pragma unroll
            for (int j = 0; j < 4; j++) {
                const float* a = acc[i][j];
                const int r0 = rr0 + i * 16;
                const int c  = cc0 + j * 8;
                bf16 h0,l0,h1,l1,h2,l2,h3,l3;
                split2(a[0],h0,l0); split2(a[1],h1,l1);
                split2(a[2],h2,l2); split2(a[3],h3,l3);
                const size_t i0 = (size_t)r0 * DIN + c;
                const size_t i1 = (size_t)(r0 + 8) * DIN + c;
                *(__nv_bfloat162*)(t_h + i0) = __nv_bfloat162(h0, h1);
                *(__nv_bfloat162*)(t_l + i0) = __nv_bfloat162(l0, l1);
                *(__nv_bfloat162*)(t_h + i1) = __nv_bfloat162(h2, h3);
                *(__nv_bfloat162*)(t_l + i1) = __nv_bfloat162(l2, l3);
            }
        }
    }
}

// ---------------------------------------------------------------------------
// Scores: S[b] = T[b] @ enc[b]^T, BM=64, BN=128, K=512, TERMS=3, fp32 out.
// grid = (16, 16, 8). S written with streaming hint (read once by softmax).
// ---------------------------------------------------------------------------
__global__ void __launch_bounds__(128, 4)
scores_kernel(const bf16* t_h, const bf16* t_l,
              const bf16* enc_h, const bf16* enc_l, float* __restrict__ S)
{
    extern __shared__ __align__(128) char smem[];
    const int z = blockIdx.z;
    const int m0 = blockIdx.y * 64;
    const int n0 = blockIdx.x * 128;

    float acc[4][4][4];
    #pragma unroll
    for (int i = 0; i < 4; i++)
        #pragma unroll
        for (int j = 0; j < 4; j++)
            #pragma unroll
            for (int e = 0; e < 4; e++) acc[i][j][e] = 0.f;

    gemm_mainloop<3, false, 2>(
        (const uint16_t*)t_h, (const uint16_t*)t_l,
        (const uint16_t*)enc_h, (const uint16_t*)enc_l,
        ((long long)z * SDEC + m0) * DIN,
        ((long long)z * SENC + n0) * DIN, DIN, acc, smem);

    const int wid = threadIdx.x >> 5, lane = threadIdx.x & 31;
    const int rr0 = m0 + (lane >> 2);
    const int cc0 = n0 + wid * 32 + (lane & 3) * 2;
    float* Sb = S + (long long)z * SDEC * SENC;

    #pragma unroll
    for (int i = 0; i < 4; i++) {
        #pragma unroll
        for (int j = 0; j < 4; j++) {
            const float* a = acc[i][j];
            const int r0 = rr0 + i * 16;
            const int c  = cc0 + j * 8;
            __stcs((float2*)(Sb + (long long)r0 * SENC + c),
                   make_float2(a[0], a[1]));
            __stcs((float2*)(Sb + (long long)(r0 + 8) * SENC + c),
                   make_float2(a[2], a[3]));
        }
    }
}

// ---------------------------------------------------------------------------
// PV: out[b] = P[b] @ V[b]. BM=64, BN=128, K=2048, fp16, NSTG=4. grid (4,16,8)
// ---------------------------------------------------------------------------
__global__ void __launch_bounds__(128, 4)
pv_kernel(const __half* P, const __half* VT, float* __restrict__ O)
{
    extern __shared__ __align__(128) char smem[];
    const int z = blockIdx.z;
    const int m0 = blockIdx.y * 64;
    const int n0 = blockIdx.x * 128;

    float acc[4][4][4];
    #pragma unroll
    for (int i = 0; i < 4; i++)
        #pragma unroll
        for (int j = 0; j < 4; j++)
            #pragma unroll
            for (int e = 0; e < 4; e++) acc[i][j][e] = 0.f;

    gemm_mainloop<1, true, 4>(
        (const uint16_t*)P, nullptr, (const uint16_t*)VT, nullptr,
        ((long long)z * SDEC + m0) * SENC,
        ((long long)z * UNITS + n0) * SENC, SENC, acc, smem);

    const int wid = threadIdx.x >> 5, lane = threadIdx.x & 31;
    const int rr0 = m0 + (lane >> 2);
    const int cc0 = n0 + wid * 32 + (lane & 3) * 2;
    float* Ob = O + (long long)z * SDEC * UNITS;

    #pragma unroll
    for (int i = 0; i < 4; i++) {
        #pragma unroll
        for (int j = 0; j < 4; j++) {
            const float* a = acc[i][j];
            const int r0 = rr0 + i * 16;
            const int c  = cc0 + j * 8;
            *(float2*)(Ob + (long long)r0 * UNITS + c)       = make_float2(a[0], a[1]);
            *(float2*)(Ob + (long long)(r0 + 8) * UNITS + c) = make_float2(a[2], a[3]);
        }
    }
}

// ---------------------------------------------------------------------------
// MT = Wk * Wq^T (fp32 SIMT, exact), split-bf16 output. 32x32 tiles, grid 16x16.
// ---------------------------------------------------------------------------
__global__ void __launch_bounds__(256)
mgemm_kernel(const float* __restrict__ Wk, const float* __restrict__ Wq,
             bf16* __restrict__ mh, bf16* __restrict__ ml)
{
    __shared__ float As[16][36];
    __shared__ float Bs[16][36];
    const int e0 = blockIdx.y * 32, d0 = blockIdx.x * 32;
    const int tid = threadIdx.x;
    const int ty = tid >> 4, tx = tid & 15;

    float c00 = 0.f, c01 = 0.f, c10 = 0.f, c11 = 0.f;

    for (int u0 = 0; u0 < 512; u0 += 16) {
        {
            const int t = tid & 127;
            const int row = t >> 2, col = (t & 3) * 4;
            if (tid < 128) {
                float4 a = *(const float4*)(Wk + (size_t)(e0 + row) * 512 + u0 + col);
                As[col+0][row] = a.x; As[col+1][row] = a.y;
                As[col+2][row] = a.z; As[col+3][row] = a.w;
            } else {
                float4 b = *(const float4*)(Wq + (size_t)(d0 + row) * 512 + u0 + col);
                Bs[col+0][row] = b.x; Bs[col+1][row] = b.y;
                Bs[col+2][row] = b.z; Bs[col+3][row] = b.w;
            }
        }
        __syncthreads();
        #pragma unroll
        for (int k = 0; k < 16; k++) {
            float a0 = As[k][ty*2], a1 = As[k][ty*2+1];
            float b0 = Bs[k][tx*2], b1 = Bs[k][tx*2+1];
            c00 += a0*b0; c01 += a0*b1; c10 += a1*b0; c11 += a1*b1;
        }
        __syncthreads();
    }
    bf16 h, l;
    size_t i0 = (size_t)(e0 + ty*2) * 512 + d0 + tx*2;
    size_t i1 = i0 + 512;
    split2(c00, h, l); mh[i0]   = h; ml[i0]   = l;
    split2(c01, h, l); mh[i0+1] = h; ml[i0+1] = l;
    split2(c10, h, l); mh[i1]   = h; ml[i1]   = l;
    split2(c11, h, l); mh[i1+1] = h; ml[i1+1] = l;
}

// ---------------------------------------------------------------------------
// Merged split kernel (4x ILP):
//   dec -> bf16 hi/lo ; enc -> bf16 hi/lo + fp16 ; Wv -> W^T fp16
// blocks: [0,1024) dec | [1024,3072) enc | [3072,3328) WvT
// ---------------------------------------------------------------------------
__global__ void __launch_bounds__(256)
split_all_kernel(const float4* __restrict__ dec, const float4* __restrict__ enc,
                 const float* __restrict__ Wv,
                 __nv_bfloat162* __restrict__ dh, __nv_bfloat162* __restrict__ dl,
                 __nv_bfloat162* __restrict__ eh, __nv_bfloat162* __restrict__ el,
                 __half2* __restrict__ e16, __half* __restrict__ v16)
{
    const int b = blockIdx.x;
    if (b < 1024) {
        const int base = b * 1024;
        float4 v[4];
        #pragma unroll
        for (int it = 0; it < 4; it++)
            v[it] = dec[base + it * 256 + threadIdx.x];
        #pragma unroll
        for (int it = 0; it < 4; it++) {
            const int i = base + it * 256 + threadIdx.x;
            bf16 h0,l0,h1,l1,h2,l2,h3,l3;
            split2(v[it].x,h0,l0); split2(v[it].y,h1,l1);
            split2(v[it].z,h2,l2); split2(v[it].w,h3,l3);
            dh[2*i]   = __nv_bfloat162(h0,h1);
            dh[2*i+1] = __nv_bfloat162(h2,h3);
            dl[2*i]   = __nv_bfloat162(l0,l1);
            dl[2*i+1] = __nv_bfloat162(l2,l3);
        }
    } else if (b < 3072) {
        const int base = (b - 1024) * 1024;
        float4 v[4];
        #pragma unroll
        for (int it = 0; it < 4; it++)
            v[it] = enc[base + it * 256 + threadIdx.x];
        #pragma unroll
        for (int it = 0; it < 4; it++) {
            const int i = base + it * 256 + threadIdx.x;
            bf16 h0,l0,h1,l1,h2,l2,h3,l3;
            split2(v[it].x,h0,l0); split2(v[it].y,h1,l1);
            split2(v[it].z,h2,l2); split2(v[it].w,h3,l3);
            eh[2*i]   = __nv_bfloat162(h0,h1);
            eh[2*i+1] = __nv_bfloat162(h2,h3);
            el[2*i]   = __nv_bfloat162(l0,l1);
            el[2*i+1] = __nv_bfloat162(l2,l3);
            e16[2*i]   = __floats2half2_rn(v[it].x, v[it].y);
            e16[2*i+1] = __floats2half2_rn(v[it].z, v[it].w);
        }
    } else {
        const int base = (b - 3072) * 1024;               // [0, 262144)
        float w[4];
        #pragma unroll
        for (int it = 0; it < 4; it++)
            w[it] = Wv[base + it * 256 + threadIdx.x];
        #pragma unroll
        for (int it = 0; it < 4; it++) {
            const int idx = base + it * 256 + threadIdx.x;
            const int k = idx >> 9, n = idx & 511;
            v16[n * 512 + k] = __float2half(w[it]);
        }
    }
}

// ---------------------------------------------------------------------------
// Row softmax over 2048 fp32 scores -> fp16 probabilities (streaming S reads)
// ---------------------------------------------------------------------------
__inline__ __device__ float warpMax(float v) {
    #pragma unroll
    for (int o = 16; o; o >>= 1) v = fmaxf(v, __shfl_xor_sync(0xffffffffu, v, o));
    return v;
}
__inline__ __device__ float warpSum(float v) {
    #pragma unroll
    for (int o = 16; o; o >>= 1) v += __shfl_xor_sync(0xffffffffu, v, o);
    return v;
}

__global__ void __launch_bounds__(256)
softmax_h(const float* __restrict__ S, __half* __restrict__ P)
{
    const long long row = blockIdx.x;
    const float4* p = (const float4*)(S + row * (long long)SENC);
    const int tid = threadIdx.x, lane = tid & 31, wid = tid >> 5;

    float4 v0 = __ldcs(&p[tid]);
    float4 v1 = __ldcs(&p[tid + 256]);

    float m = fmaxf(fmaxf(fmaxf(v0.x, v0.y), fmaxf(v0.z, v0.w)),
                    fmaxf(fmaxf(v1.x, v1.y), fmaxf(v1.z, v1.w)));
    __shared__ float smax[8], ssum[8];
    m = warpMax(m);
    if (lane == 0) smax[wid] = m;
    __syncthreads();
    float bm = smax[0];
    #pragma unroll
    for (int i = 1; i < 8; i++) bm = fmaxf(bm, smax[i]);

    v0.x = __expf(v0.x - bm); v0.y = __expf(v0.y - bm);
    v0.z = __expf(v0.z - bm); v0.w = __expf(v0.w - bm);
    v1.x = __expf(v1.x - bm); v1.y = __expf(v1.y - bm);
    v1.z = __expf(v1.z - bm); v1.w = __expf(v1.w - bm);

    float s = (v0.x + v0.y + v0.z + v0.w) + (v1.x + v1.y + v1.z + v1.w);
    s = warpSum(s);
    if (lane == 0) ssum[wid] = s;
    __syncthreads();
    float bs = 0.f;
    #pragma unroll
    for (int i = 0; i < 8; i++) bs += ssum[i];
    const float inv = 1.0f / bs;

    __half2* ph = (__half2*)(P + row * (long long)SENC);
    ph[2*tid]         = __floats2half2_rn(v0.x * inv, v0.y * inv);
    ph[2*tid+1]       = __floats2half2_rn(v0.z * inv, v0.w * inv);
    ph[512 + 2*tid]   = __floats2half2_rn(v1.x * inv, v1.y * inv);
    ph[512 + 2*tid+1] = __floats2half2_rn(v1.z * inv, v1.w * inv);
}

// ---------------------------------------------------------------------------
extern "C" void kernel_launch(void* const* d_in, const int* in_sizes, int n_in,
                              void* d_out, int out_size)
{
    const float* enc = (const float*)d_in[0];
    const float* dec = (const float*)d_in[1];
    const float* Wq  = (const float*)d_in[2];
    const float* Wk  = (const float*)d_in[3];
    const float* Wv  = (const float*)d_in[4];
    float* out = (float*)d_out;

    bf16 *dec_h,*dec_l,*enc_h,*enc_l,*mt_h,*mt_l,*t_h,*t_l;
    __half *enc16, *wvT16, *vt16, *p16;
    float *s;
    cudaGetSymbolAddress((void**)&dec_h, g_dec_h);
    cudaGetSymbolAddress((void**)&dec_l, g_dec_l);
    cudaGetSymbolAddress((void**)&enc_h, g_enc_h);
    cudaGetSymbolAddress((void**)&enc_l, g_enc_l);
    cudaGetSymbolAddress((void**)&enc16, g_enc16);
    cudaGetSymbolAddress((void**)&wvT16, g_wvT16);
    cudaGetSymbolAddress((void**)&mt_h, g_mt_h);
    cudaGetSymbolAddress((void**)&mt_l, g_mt_l);
    cudaGetSymbolAddress((void**)&t_h, g_t_h);
    cudaGetSymbolAddress((void**)&t_l, g_t_l);
    cudaGetSymbolAddress((void**)&vt16, g_vt16);
    cudaGetSymbolAddress((void**)&p16, g_p16);
    cudaGetSymbolAddress((void**)&s, g_s);

    cudaFuncSetAttribute(proj2_kernel,  cudaFuncAttributeMaxDynamicSharedMemorySize, SMEM_F1);
    cudaFuncSetAttribute(scores_kernel, cudaFuncAttributeMaxDynamicSharedMemorySize, SMEM_G3);
    cudaFuncSetAttribute(pv_kernel,     cudaFuncAttributeMaxDynamicSharedMemorySize, SMEM_F1);

    // 1. input splits (dec, enc, Wv^T)
    split_all_kernel<<<3328, 256>>>(
        (const float4*)dec, (const float4*)enc, Wv,
        (__nv_bfloat162*)dec_h, (__nv_bfloat162*)dec_l,
        (__nv_bfloat162*)enc_h, (__nv_bfloat162*)enc_l,
        (__half2*)enc16, wvT16);

    // 2. MT = Wk * Wq^T (exact fp32) -> split bf16
    mgemm_kernel<<<dim3(16, 16), 256>>>(Wk, Wq, mt_h, mt_l);

    // 3. merged projections: V^T (fp16) + T (3-term)
    proj2_kernel<<<dim3(4, 384), 128, SMEM_F1>>>(
        dec_h, dec_l, mt_h, mt_l, enc16, wvT16, t_h, t_l, vt16);

    // 4. scores S = T @ enc^T (batched)
    scores_kernel<<<dim3(16, 16, 8), 128, SMEM_G3>>>(t_h, t_l, enc_h, enc_l, s);

    // 5. softmax -> fp16 P
    softmax_h<<<NB * SDEC, 256>>>(s, p16);

    // 6. out = P @ V
    pv_kernel<<<dim3(4, 16, 8), 128, SMEM_F1>>>(p16, vt16, out);
}

// round 16
// speedup vs baseline: 1.0537x; 1.0115x over previous
#include <cuda_runtime.h>
#include <cuda_bf16.h>
#include <cuda_fp16.h>
#include <cstdint>

#define NB    8
#define SENC  2048
#define SDEC  1024
#define DIN   512
#define UNITS 512

using bf16 = __nv_bfloat16;

// ---------------------------------------------------------------------------
// Scratch (__device__ globals: allocation-free rule)
// ---------------------------------------------------------------------------
__device__ __align__(256) bf16 g_dec_h[(size_t)NB * SDEC * DIN];
__device__ __align__(256) bf16 g_dec_l[(size_t)NB * SDEC * DIN];
__device__ __align__(256) bf16 g_enc_h[(size_t)NB * SENC * DIN];
__device__ __align__(256) bf16 g_enc_l[(size_t)NB * SENC * DIN];
__device__ __align__(256) __half g_enc16[(size_t)NB * SENC * DIN];  // enc fp16
__device__ __align__(256) __half g_wvT16[DIN * UNITS];              // Wv^T fp16
__device__ __align__(256) bf16 g_mt_h[DIN * DIN];      // MT[e][d] = (Wq Wk^T)^T
__device__ __align__(256) bf16 g_mt_l[DIN * DIN];
__device__ __align__(256) bf16 g_t_h[(size_t)NB * SDEC * DIN];   // T = dec*M
__device__ __align__(256) bf16 g_t_l[(size_t)NB * SDEC * DIN];
__device__ __align__(256) __half g_vt16[(size_t)NB * UNITS * SENC]; // V^T fp16
__device__ __align__(256) float g_s[(size_t)NB * SDEC * SENC];      // fp32 scores
__device__ __align__(256) __half g_p16[(size_t)NB * SDEC * SENC];   // P fp16

// ---------------------------------------------------------------------------
// helpers
// ---------------------------------------------------------------------------
__device__ __forceinline__ void split2(float x, bf16& h, bf16& l) {
    h = __float2bfloat16(x);
    l = __float2bfloat16(x - __bfloat162float(h));
}

#define CPA(dst, src) asm volatile( \
    "cp.async.cg.shared.global [%0], [%1], 16;" :: "r"(dst), "l"(src))
#define CP_COMMIT() asm volatile("cp.async.commit_group;")

template <int N>
__device__ __forceinline__ void cp_wait() {
    asm volatile("cp.async.wait_group %0;" :: "n"(N));
}

#define LDSM4(r0,r1,r2,r3,addr) asm volatile( \
    "ldmatrix.sync.aligned.m8n8.x4.shared.b16 {%0,%1,%2,%3}, [%4];" \
    : "=r"(r0),"=r"(r1),"=r"(r2),"=r"(r3) : "r"(addr))

#define MMA_BF16(ac,Af,B0,B1) asm volatile( \
    "mma.sync.aligned.m16n8k16.row.col.f32.bf16.bf16.f32 " \
    "{%0,%1,%2,%3}, {%4,%5,%6,%7}, {%8,%9}, {%0,%1,%2,%3};" \
    : "+f"(ac[0]),"+f"(ac[1]),"+f"(ac[2]),"+f"(ac[3]) \
    : "r"(Af[0]),"r"(Af[1]),"r"(Af[2]),"r"(Af[3]), "r"(B0),"r"(B1))

#define MMA_FP16(ac,Af,B0,B1) asm volatile( \
    "mma.sync.aligned.m16n8k16.row.col.f32.f16.f16.f32 " \
    "{%0,%1,%2,%3}, {%4,%5,%6,%7}, {%8,%9}, {%0,%1,%2,%3};" \
    : "+f"(ac[0]),"+f"(ac[1]),"+f"(ac[2]),"+f"(ac[3]) \
    : "r"(Af[0]),"r"(Af[1]),"r"(Af[2]),"r"(Af[3]), "r"(B0),"r"(B1))

// XOR-swizzled smem offset for a (row, 16B-chunk) of a 64B-wide tile.
__device__ __forceinline__ uint32_t swz(int row, int c) {
    return (uint32_t)(row * 64 + ((c ^ ((row >> 1) & 3)) << 4));
}

// ---------------------------------------------------------------------------
// 4-warp NT GEMM mainloop (R9 configuration — single-buffered fragments).
// BM=64, BN=128, BK=32; warps as 1x4 (warp tile 64x32). TERMS=3: bf16 hi/lo
// split (3 MMA terms). TERMS=1 & FP16: plain fp16. XOR-swizzled unpadded
// smem. Single-sync software pipeline. acc[4][4][4] fp32.
// ---------------------------------------------------------------------------
template <int TERMS, bool FP16, int NSTG>
__device__ __forceinline__ void gemm_mainloop(
    const uint16_t* __restrict__ Ah, const uint16_t* __restrict__ Al,
    const uint16_t* __restrict__ Bh, const uint16_t* __restrict__ Bl,
    long long aBase, long long bBase, int K,
    float acc[4][4][4], char* smem)
{
    constexpr int A_TB = 64 * 64;       // 4096 B
    constexpr int B_TB = 128 * 64;      // 8192 B
    constexpr int BOFF = (TERMS == 3) ? 2 * A_TB : A_TB;
    constexpr int STG  = (TERMS == 3) ? 2 * (A_TB + B_TB) : (A_TB + B_TB);

    const int tid  = threadIdx.x;
    const int wid  = tid >> 5;
    const int lane = tid & 31;
    const int wn = wid * 32;

    const uint32_t sm0 = (uint32_t)__cvta_generic_to_shared(smem);

    const int a_row = (lane & 7) + ((lane >> 3) & 1) * 8;
    const int a_kc  = ((lane >> 4) & 1);        // k-chunk (16B) within k16
    const int b_row = (lane & 7) + ((lane >> 4) & 1) * 8;
    const int b_kc  = ((lane >> 3) & 1);

    const int nk = K / 32;

    auto load_stage = [&](int s, int k0) {
        const uint32_t st = sm0 + s * STG;
        #pragma unroll
        for (int c = tid; c < 256; c += 128) {        // A: 64 rows x 4 chunks
            const int row = c >> 2, ch = c & 3;
            const uint32_t sa = st + swz(row, ch);
            const long long g = aBase + (long long)row * K + k0 + ch * 8;
            CPA(sa, Ah + g);
            if (TERMS == 3) CPA(sa + A_TB, Al + g);
        }
        #pragma unroll
        for (int c = tid; c < 512; c += 128) {        // B: 128 rows x 4 chunks
            const int row = c >> 2, ch = c & 3;
            const uint32_t sb = st + BOFF + swz(row, ch);
            const long long g = bBase + (long long)row * K + k0 + ch * 8;
            CPA(sb, Bh + g);
            if (TERMS == 3) CPA(sb + B_TB, Bl + g);
        }
    };

    #pragma unroll
    for (int s = 0; s < NSTG - 1; s++) {
        load_stage(s, s * 32);
        CP_COMMIT();
    }

    for (int kt = 0; kt < nk; kt++) {
        cp_wait<NSTG - 2>();
        __syncthreads();

        const int knext = kt + NSTG - 1;
        if (knext < nk)
            load_stage(knext % NSTG, knext * 32);     // overlaps compute
        CP_COMMIT();

        const uint32_t st  = sm0 + (kt % NSTG) * STG;
        const uint32_t stA = st, stB = st + BOFF;

        #pragma unroll
        for (int ks = 0; ks < 2; ks++) {
            const int kc = ks * 2;                    // 16B chunk base of k16
            uint32_t ah[4][4], al[4][4];
            #pragma unroll
            for (int i = 0; i < 4; i++) {
                const int row = i * 16 + a_row;
                const uint32_t off = swz(row, kc + a_kc);
                LDSM4(ah[i][0], ah[i][1], ah[i][2], ah[i][3], stA + off);
                if (TERMS == 3)
                    LDSM4(al[i][0], al[i][1], al[i][2], al[i][3], stA + A_TB + off);
            }
            #pragma unroll
            for (int j2 = 0; j2 < 2; j2++) {
                uint32_t bh[4], bl[4];
                const int row = wn + j2 * 16 + b_row;
                const uint32_t off = swz(row, kc + b_kc);
                LDSM4(bh[0], bh[1], bh[2], bh[3], stB + off);
                if (TERMS == 3)
                    LDSM4(bl[0], bl[1], bl[2], bl[3], stB + B_TB + off);
                #pragma unroll
                for (int i = 0; i < 4; i++) {
                    if (FP16) {
                        MMA_FP16(acc[i][2*j2],   ah[i], bh[0], bh[1]);
                        MMA_FP16(acc[i][2*j2+1], ah[i], bh[2], bh[3]);
                    } else {
                        MMA_BF16(acc[i][2*j2],   ah[i], bh[0], bh[1]);
                        MMA_BF16(acc[i][2*j2+1], ah[i], bh[2], bh[3]);
                        if (TERMS == 3) {
                            MMA_BF16(acc[i][2*j2],   ah[i], bl[0], bl[1]);
                            MMA_BF16(acc[i][2*j2],   al[i], bh[0], bh[1]);
                            MMA_BF16(acc[i][2*j2+1], ah[i], bl[2], bl[3]);
                            MMA_BF16(acc[i][2*j2+1], al[i], bh[2], bh[3]);
                        }
                    }
                }
            }
        }
    }
}

constexpr int SMEM_G3 = 2 * 2 * (64 * 64 + 128 * 64);   // 49152 (TERMS=3, NST=2)
constexpr int SMEM_F1 = 4 * (64 * 64 + 128 * 64);       // 49152 (fp16, NST=4)

// ---------------------------------------------------------------------------
// Merged projection kernel: grid (4, 384).
//   y < 256 : V^T = enc16 @ WvT16^T (fp16 single-term, NSTG=4)
//   y >= 256: T = dec @ M (TERMS=3 bf16, NSTG=2), split-bf16 epilogue
// ---------------------------------------------------------------------------
__global__ void __launch_bounds__(128, 4)
proj2_kernel(const bf16* dec_h, const bf16* dec_l,
             const bf16* mt_h, const bf16* mt_l,
             const __half* enc16, const __half* wvT16,
             bf16* t_h, bf16* t_l, __half* vt)
{
    extern __shared__ __align__(128) char smem[];
    const int y = blockIdx.y;
    const int n0 = blockIdx.x * 128;
    const int wid = threadIdx.x >> 5, lane = threadIdx.x & 31;

    float acc[4][4][4];
    #pragma unroll
    for (int i = 0; i < 4; i++)
        #pragma unroll
        for (int j = 0; j < 4; j++)
            #pragma unroll
            for (int e = 0; e < 4; e++) acc[i][j][e] = 0.f;

    if (y < 256) {
        // ---- V projection (fp16 single-term) ----
        const int arow0 = y * 64;
        gemm_mainloop<1, true, 4>(
            (const uint16_t*)enc16, nullptr,
            (const uint16_t*)wvT16, nullptr,
            (long long)arow0 * DIN, (long long)n0 * DIN, DIN, acc, smem);

        const int rr0 = arow0 + (lane >> 2);
        const int cc0 = n0 + wid * 32 + (lane & 3) * 2;
        #pragma unroll
        for (int i = 0; i < 4; i++) {
            #pragma unroll
            for (int j = 0; j < 4; j++) {
                const float* a = acc[i][j];
                const int r0 = rr0 + i * 16;
                const int c  = cc0 + j * 8;
                #pragma unroll
                for (int e = 0; e < 4; e++) {
                    const int rr = r0 + (e >> 1) * 8;        // enc row
                    const int cn = c + (e & 1);              // unit
                    const size_t idx = (size_t)(rr >> 11) * ((size_t)UNITS * SENC)
                                     + (size_t)cn * SENC + (rr & 2047);
                    vt[idx] = __float2half(a[e]);
                }
            }
        }
    } else {
        // ---- T projection (3-term bf16) ----
        const int arow0 = (y - 256) * 64;
        gemm_mainloop<3, false, 2>(
            (const uint16_t*)dec_h, (const uint16_t*)dec_l,
            (const uint16_t*)mt_h, (const uint16_t*)mt_l,
            (long long)arow0 * DIN, (long long)n0 * DIN, DIN, acc, smem);

        const int rr0 = arow0 + (lane >> 2);
        const int cc0 = n0 + wid * 32 + (lane & 3) * 2;
        #pragma unroll
        for (int i = 0; i < 4; i++) {
            #pragma unroll
            for (int j = 0; j < 4; j++) {
                const float* a = acc[i][j];
                const int r0 = rr0 + i * 16;
                const int c  = cc0 + j * 8;
                bf16 h0,l0,h1,l1,h2,l2,h3,l3;
                split2(a[0],h0,l0); split2(a[1],h1,l1);
                split2(a[2],h2,l2); split2(a[3],h3,l3);
                const size_t i0 = (size_t)r0 * DIN + c;
                const size_t i1 = (size_t)(r0 + 8) * DIN + c;
                *(__nv_bfloat162*)(t_h + i0) = __nv_bfloat162(h0, h1);
                *(__nv_bfloat162*)(t_l + i0) = __nv_bfloat162(l0, l1);
                *(__nv_bfloat162*)(t_h + i1) = __nv_bfloat162(h2, h3);
                *(__nv_bfloat162*)(t_l + i1) = __nv_bfloat162(l2, l3);
            }
        }
    }
}

// ---------------------------------------------------------------------------
// Scores: S[b] = T[b] @ enc[b]^T, BM=64, BN=128, K=512, TERMS=3, fp32 out.
// grid = (16, 16, 8). S written with streaming hint (read once by softmax).
// ---------------------------------------------------------------------------
__global__ void __launch_bounds__(128, 4)
scores_kernel(const bf16* t_h, const bf16* t_l,
              const bf16* enc_h, const bf16* enc_l, float* __restrict__ S)
{
    extern __shared__ __align__(128) char smem[];
    const int z = blockIdx.z;
    const int m0 = blockIdx.y * 64;
    const int n0 = blockIdx.x * 128;

    float acc[4][4][4];
    #pragma unroll
    for (int i = 0; i < 4; i++)
        #pragma unroll
        for (int j = 0; j < 4; j++)
            #pragma unroll
            for (int e = 0; e < 4; e++) acc[i][j][e] = 0.f;

    gemm_mainloop<3, false, 2>(
        (const uint16_t*)t_h, (const uint16_t*)t_l,
        (const uint16_t*)enc_h, (const uint16_t*)enc_l,
        ((long long)z * SDEC + m0) * DIN,
        ((long long)z * SENC + n0) * DIN, DIN, acc, smem);

    const int wid = threadIdx.x >> 5, lane = threadIdx.x & 31;
    const int rr0 = m0 + (lane >> 2);
    const int cc0 = n0 + wid * 32 + (lane & 3) * 2;
    float* Sb = S + (long long)z * SDEC * SENC;

    #pragma unroll
    for (int i = 0; i < 4; i++) {
        #pragma unroll
        for (int j = 0; j < 4; j++) {
            const float* a = acc[i][j];
            const int r0 = rr0 + i * 16;
            const int c  = cc0 + j * 8;
            __stcs((float2*)(Sb + (long long)r0 * SENC + c),
                   make_float2(a[0], a[1]));
            __stcs((float2*)(Sb + (long long)(r0 + 8) * SENC + c),
                   make_float2(a[2], a[3]));
        }
    }
}

// ---------------------------------------------------------------------------
// PV: out[b] = P[b] @ V[b]. BM=64, BN=128, K=2048, fp16, NSTG=4. grid (4,16,8)
// ---------------------------------------------------------------------------
__global__ void __launch_bounds__(128, 4)
pv_kernel(const __half* P, const __half* VT, float* __restrict__ O)
{
    extern __shared__ __align__(128) char smem[];
    const int z = blockIdx.z;
    const int m0 = blockIdx.y * 64;
    const int n0 = blockIdx.x * 128;

    float acc[4][4][4];
    #pragma unroll
    for (int i = 0; i < 4; i++)
        #pragma unroll
        for (int j = 0; j < 4; j++)
            #pragma unroll
            for (int e = 0; e < 4; e++) acc[i][j][e] = 0.f;

    gemm_mainloop<1, true, 4>(
        (const uint16_t*)P, nullptr, (const uint16_t*)VT, nullptr,
        ((long long)z * SDEC + m0) * SENC,
        ((long long)z * UNITS + n0) * SENC, SENC, acc, smem);

    const int wid = threadIdx.x >> 5, lane = threadIdx.x & 31;
    const int rr0 = m0 + (lane >> 2);
    const int cc0 = n0 + wid * 32 + (lane & 3) * 2;
    float* Ob = O + (long long)z * SDEC * UNITS;

    #pragma unroll
    for (int i = 0; i < 4; i++) {
        #pragma unroll
        for (int j = 0; j < 4; j++) {
            const float* a = acc[i][j];
            const int r0 = rr0 + i * 16;
            const int c  = cc0 + j * 8;
            *(float2*)(Ob + (long long)r0 * UNITS + c)       = make_float2(a[0], a[1]);
            *(float2*)(Ob + (long long)(r0 + 8) * UNITS + c) = make_float2(a[2], a[3]);
        }
    }
}

// ---------------------------------------------------------------------------
// Merged prep kernel (256 threads). MGEMM BLOCKS FIRST (they are the longest;
// starting them in wave 1 lets them overlap the split blocks instead of
// extending the tail):
//  blocks [0,256):     MT = Wk*Wq^T (fp32 exact) -> split bf16 (32x32 tile)
//  blocks [256,1280):  dec -> bf16 hi/lo           (4x ILP)
//  blocks [1280,3328): enc -> bf16 hi/lo + fp16    (4x ILP)
//  blocks [3328,3584): Wv  -> Wv^T fp16            (4x ILP)
// ---------------------------------------------------------------------------
__global__ void __launch_bounds__(256)
prep_kernel(const float4* __restrict__ dec, const float4* __restrict__ enc,
            const float* __restrict__ Wv,
            const float* __restrict__ Wk, const float* __restrict__ Wq,
            __nv_bfloat162* __restrict__ dh, __nv_bfloat162* __restrict__ dl,
            __nv_bfloat162* __restrict__ eh, __nv_bfloat162* __restrict__ el,
            __half2* __restrict__ e16, __half* __restrict__ v16,
            bf16* __restrict__ mh, bf16* __restrict__ ml)
{
    const int b = blockIdx.x;
    if (b < 256) {
        // ---- MT = Wk * Wq^T (exact fp32 SIMT) ----
        __shared__ float As[16][36];
        __shared__ float Bs[16][36];
        const int e0 = (b >> 4) * 32, d0 = (b & 15) * 32;
        const int tid = threadIdx.x;
        const int ty = tid >> 4, tx = tid & 15;

        float c00 = 0.f, c01 = 0.f, c10 = 0.f, c11 = 0.f;

        for (int u0 = 0; u0 < 512; u0 += 16) {
            {
                const int t = tid & 127;
                const int row = t >> 2, col = (t & 3) * 4;
                if (tid < 128) {
                    float4 a = *(const float4*)(Wk + (size_t)(e0 + row) * 512 + u0 + col);
                    As[col+0][row] = a.x; As[col+1][row] = a.y;
                    As[col+2][row] = a.z; As[col+3][row] = a.w;
                } else {
                    float4 bb = *(const float4*)(Wq + (size_t)(d0 + row) * 512 + u0 + col);
                    Bs[col+0][row] = bb.x; Bs[col+1][row] = bb.y;
                    Bs[col+2][row] = bb.z; Bs[col+3][row] = bb.w;
                }
            }
            __syncthreads();
            #pragma unroll
            for (int k = 0; k < 16; k++) {
                float a0 = As[k][ty*2], a1 = As[k][ty*2+1];
                float b0 = Bs[k][tx*2], b1 = Bs[k][tx*2+1];
                c00 += a0*b0; c01 += a0*b1; c10 += a1*b0; c11 += a1*b1;
            }
            __syncthreads();
        }
        bf16 h, l;
        size_t i0 = (size_t)(e0 + ty*2) * 512 + d0 + tx*2;
        size_t i1 = i0 + 512;
        split2(c00, h, l); mh[i0]   = h; ml[i0]   = l;
        split2(c01, h, l); mh[i0+1] = h; ml[i0+1] = l;
        split2(c10, h, l); mh[i1]   = h; ml[i1]   = l;
        split2(c11, h, l); mh[i1+1] = h; ml[i1+1] = l;
    } else if (b < 1280) {
        const int base = (b - 256) * 1024;
        float4 v[4];
        #pragma unroll
        for (int it = 0; it < 4; it++)
            v[it] = dec[base + it * 256 + threadIdx.x];
        #pragma unroll
        for (int it = 0; it < 4; it++) {
            const int i = base + it * 256 + threadIdx.x;
            bf16 h0,l0,h1,l1,h2,l2,h3,l3;
            split2(v[it].x,h0,l0); split2(v[it].y,h1,l1);
            split2(v[it].z,h2,l2); split2(v[it].w,h3,l3);
            dh[2*i]   = __nv_bfloat162(h0,h1);
            dh[2*i+1] = __nv_bfloat162(h2,h3);
            dl[2*i]   = __nv_bfloat162(l0,l1);
            dl[2*i+1] = __nv_bfloat162(l2,l3);
        }
    } else if (b < 3328) {
        const int base = (b - 1280) * 1024;
        float4 v[4];
        #pragma unroll
        for (int it = 0; it < 4; it++)
            v[it] = enc[base + it * 256 + threadIdx.x];
        #pragma unroll
        for (int it = 0; it < 4; it++) {
            const int i = base + it * 256 + threadIdx.x;
            bf16 h0,l0,h1,l1,h2,l2,h3,l3;
            split2(v[it].x,h0,l0); split2(v[it].y,h1,l1);
            split2(v[it].z,h2,l2); split2(v[it].w,h3,l3);
            eh[2*i]   = __nv_bfloat162(h0,h1);
            eh[2*i+1] = __nv_bfloat162(h2,h3);
            el[2*i]   = __nv_bfloat162(l0,l1);
            el[2*i+1] = __nv_bfloat162(l2,l3);
            e16[2*i]   = __floats2half2_rn(v[it].x, v[it].y);
            e16[2*i+1] = __floats2half2_rn(v[it].z, v[it].w);
        }
    } else {
        const int base = (b - 3328) * 1024;               // [0, 262144)
        float w[4];
        #pragma unroll
        for (int it = 0; it < 4; it++)
            w[it] = Wv[base + it * 256 + threadIdx.x];
        #pragma unroll
        for (int it = 0; it < 4; it++) {
            const int idx = base + it * 256 + threadIdx.x;
            const int k = idx >> 9, n = idx & 511;
            v16[n * 512 + k] = __float2half(w[it]);
        }
    }
}

// ---------------------------------------------------------------------------
// Row softmax over 2048 fp32 scores -> fp16 probabilities (streaming S reads)
// ---------------------------------------------------------------------------
__inline__ __device__ float warpMax(float v) {
    #pragma unroll
    for (int o = 16; o; o >>= 1) v = fmaxf(v, __shfl_xor_sync(0xffffffffu, v, o));
    return v;
}
__inline__ __device__ float warpSum(float v) {
    #pragma unroll
    for (int o = 16; o; o >>= 1) v += __shfl_xor_sync(0xffffffffu, v, o);
    return v;
}

__global__ void __launch_bounds__(256)
softmax_h(const float* __restrict__ S, __half* __restrict__ P)
{
    const long long row = blockIdx.x;
    const float4* p = (const float4*)(S + row * (long long)SENC);
    const int tid = threadIdx.x, lane = tid & 31, wid = tid >> 5;

    float4 v0 = __ldcs(&p[tid]);
    float4 v1 = __ldcs(&p[tid + 256]);

    float m = fmaxf(fmaxf(fmaxf(v0.x, v0.y), fmaxf(v0.z, v0.w)),
                    fmaxf(fmaxf(v1.x, v1.y), fmaxf(v1.z, v1.w)));
    __shared__ float smax[8], ssum[8];
    m = warpMax(m);
    if (lane == 0) smax[wid] = m;
    __syncthreads();
    float bm = smax[0];
    #pragma unroll
    for (int i = 1; i < 8; i++) bm = fmaxf(bm, smax[i]);

    v0.x = __expf(v0.x - bm); v0.y = __expf(v0.y - bm);
    v0.z = __expf(v0.z - bm); v0.w = __expf(v0.w - bm);
    v1.x = __expf(v1.x - bm); v1.y = __expf(v1.y - bm);
    v1.z = __expf(v1.z - bm); v1.w = __expf(v1.w - bm);

    float s = (v0.x + v0.y + v0.z + v0.w) + (v1.x + v1.y + v1.z + v1.w);
    s = warpSum(s);
    if (lane == 0) ssum[wid] = s;
    __syncthreads();
    float bs = 0.f;
    #pragma unroll
    for (int i = 0; i < 8; i++) bs += ssum[i];
    const float inv = 1.0f / bs;

    __half2* ph = (__half2*)(P + row * (long long)SENC);
    ph[2*tid]         = __floats2half2_rn(v0.x * inv, v0.y * inv);
    ph[2*tid+1]       = __floats2half2_rn(v0.z * inv, v0.w * inv);
    ph[512 + 2*tid]   = __floats2half2_rn(v1.x * inv, v1.y * inv);
    ph[512 + 2*tid+1] = __floats2half2_rn(v1.z * inv, v1.w * inv);
}

// ---------------------------------------------------------------------------
extern "C" void kernel_launch(void* const* d_in, const int* in_sizes, int n_in,
                              void* d_out, int out_size)
{
    const float* enc = (const float*)d_in[0];
    const float* dec = (const float*)d_in[1];
    const float* Wq  = (const float*)d_in[2];
    const float* Wk  = (const float*)d_in[3];
    const float* Wv  = (const float*)d_in[4];
    float* out = (float*)d_out;

    bf16 *dec_h,*dec_l,*enc_h,*enc_l,*mt_h,*mt_l,*t_h,*t_l;
    __half *enc16, *wvT16, *vt16, *p16;
    float *s;
    cudaGetSymbolAddress((void**)&dec_h, g_dec_h);
    cudaGetSymbolAddress((void**)&dec_l, g_dec_l);
    cudaGetSymbolAddress((void**)&enc_h, g_enc_h);
    cudaGetSymbolAddress((void**)&enc_l, g_enc_l);
    cudaGetSymbolAddress((void**)&enc16, g_enc16);
    cudaGetSymbolAddress((void**)&wvT16, g_wvT16);
    cudaGetSymbolAddress((void**)&mt_h, g_mt_h);
    cudaGetSymbolAddress((void**)&mt_l, g_mt_l);
    cudaGetSymbolAddress((void**)&t_h, g_t_h);
    cudaGetSymbolAddress((void**)&t_l, g_t_l);
    cudaGetSymbolAddress((void**)&vt16, g_vt16);
    cudaGetSymbolAddress((void**)&p16, g_p16);
    cudaGetSymbolAddress((void**)&s, g_s);

    cudaFuncSetAttribute(proj2_kernel,  cudaFuncAttributeMaxDynamicSharedMemorySize, SMEM_F1);
    cudaFuncSetAttribute(scores_kernel, cudaFuncAttributeMaxDynamicSharedMemorySize, SMEM_G3);
    cudaFuncSetAttribute(pv_kernel,     cudaFuncAttributeMaxDynamicSharedMemorySize, SMEM_F1);

    // 1. all prep in one launch (mgemm blocks FIRST so they overlap splits)
    prep_kernel<<<3584, 256>>>(
        (const float4*)dec, (const float4*)enc, Wv, Wk, Wq,
        (__nv_bfloat162*)dec_h, (__nv_bfloat162*)dec_l,
        (__nv_bfloat162*)enc_h, (__nv_bfloat162*)enc_l,
        (__half2*)enc16, wvT16, mt_h, mt_l);

    // 2. merged projections: V^T (fp16) + T (3-term)
    proj2_kernel<<<dim3(4, 384), 128, SMEM_F1>>>(
        dec_h, dec_l, mt_h, mt_l, enc16, wvT16, t_h, t_l, vt16);

    // 3. scores S = T @ enc^T (batched)
    scores_kernel<<<dim3(16, 16, 8), 128, SMEM_G3>>>(t_h, t_l, enc_h, enc_l, s);

    // 4. softmax -> fp16 P
    softmax_h<<<NB * SDEC, 256>>>(s, p16);

    // 5. out = P @ V
    pv_kernel<<<dim3(4, 16, 8), 128, SMEM_F1>>>(p16, vt16, out);
}

// round 17
// speedup vs baseline: 1.0681x; 1.0136x over previous
#include <cuda_runtime.h>
#include <cuda_bf16.h>
#include <cuda_fp16.h>
#include <cstdint>

#define NB    8
#define SENC  2048
#define SDEC  1024
#define DIN   512
#define UNITS 512

using bf16 = __nv_bfloat16;

// ---------------------------------------------------------------------------
// Scratch (__device__ globals: allocation-free rule)
// ---------------------------------------------------------------------------
__device__ __align__(256) bf16 g_dec_h[(size_t)NB * SDEC * DIN];
__device__ __align__(256) bf16 g_dec_l[(size_t)NB * SDEC * DIN];
__device__ __align__(256) bf16 g_enc_h[(size_t)NB * SENC * DIN];
__device__ __align__(256) bf16 g_enc_l[(size_t)NB * SENC * DIN];
__device__ __align__(256) __half g_enc16[(size_t)NB * SENC * DIN];  // enc fp16
__device__ __align__(256) __half g_wvT16[DIN * UNITS];              // Wv^T fp16
__device__ __align__(256) bf16 g_mt_h[DIN * DIN];      // MT[e][d] = (Wq Wk^T)^T
__device__ __align__(256) bf16 g_mt_l[DIN * DIN];
__device__ __align__(256) bf16 g_t_h[(size_t)NB * SDEC * DIN];   // T = dec*M
__device__ __align__(256) bf16 g_t_l[(size_t)NB * SDEC * DIN];
__device__ __align__(256) __half g_vt16[(size_t)NB * UNITS * SENC]; // V^T fp16
__device__ __align__(256) float g_s[(size_t)NB * SDEC * SENC];      // fp32 scores
__device__ __align__(256) __half g_p16[(size_t)NB * SDEC * SENC];   // P fp16

// ---------------------------------------------------------------------------
// helpers
// ---------------------------------------------------------------------------
__device__ __forceinline__ void split2(float x, bf16& h, bf16& l) {
    h = __float2bfloat16(x);
    l = __float2bfloat16(x - __bfloat162float(h));
}

#define CPA(dst, src) asm volatile( \
    "cp.async.cg.shared.global [%0], [%1], 16;" :: "r"(dst), "l"(src))
#define CP_COMMIT() asm volatile("cp.async.commit_group;")

template <int N>
__device__ __forceinline__ void cp_wait() {
    asm volatile("cp.async.wait_group %0;" :: "n"(N));
}

#define LDSM4(r0,r1,r2,r3,addr) asm volatile( \
    "ldmatrix.sync.aligned.m8n8.x4.shared.b16 {%0,%1,%2,%3}, [%4];" \
    : "=r"(r0),"=r"(r1),"=r"(r2),"=r"(r3) : "r"(addr))

#define MMA_BF16(ac,Af,B0,B1) asm volatile( \
    "mma.sync.aligned.m16n8k16.row.col.f32.bf16.bf16.f32 " \
    "{%0,%1,%2,%3}, {%4,%5,%6,%7}, {%8,%9}, {%0,%1,%2,%3};" \
    : "+f"(ac[0]),"+f"(ac[1]),"+f"(ac[2]),"+f"(ac[3]) \
    : "r"(Af[0]),"r"(Af[1]),"r"(Af[2]),"r"(Af[3]), "r"(B0),"r"(B1))

#define MMA_FP16(ac,Af,B0,B1) asm volatile( \
    "mma.sync.aligned.m16n8k16.row.col.f32.f16.f16.f32 " \
    "{%0,%1,%2,%3}, {%4,%5,%6,%7}, {%8,%9}, {%0,%1,%2,%3};" \
    : "+f"(ac[0]),"+f"(ac[1]),"+f"(ac[2]),"+f"(ac[3]) \
    : "r"(Af[0]),"r"(Af[1]),"r"(Af[2]),"r"(Af[3]), "r"(B0),"r"(B1))

// XOR-swizzled smem offset for a (row, 16B-chunk) of a 64B-wide tile.
__device__ __forceinline__ uint32_t swz(int row, int c) {
    return (uint32_t)(row * 64 + ((c ^ ((row >> 1) & 3)) << 4));
}

// ---------------------------------------------------------------------------
// 4-warp NT GEMM mainloop (R9 configuration — single-buffered fragments).
// BM=64, BN=128, BK=32; warps as 1x4 (warp tile 64x32). TERMS=3: bf16 hi/lo
// split (3 MMA terms). TERMS=1 & FP16: plain fp16. XOR-swizzled unpadded
// smem. Single-sync software pipeline. acc[4][4][4] fp32.
// ---------------------------------------------------------------------------
template <int TERMS, bool FP16, int NSTG>
__device__ __forceinline__ void gemm_mainloop(
    const uint16_t* __restrict__ Ah, const uint16_t* __restrict__ Al,
    const uint16_t* __restrict__ Bh, const uint16_t* __restrict__ Bl,
    long long aBase, long long bBase, int K,
    float acc[4][4][4], char* smem)
{
    constexpr int A_TB = 64 * 64;       // 4096 B
    constexpr int B_TB = 128 * 64;      // 8192 B
    constexpr int BOFF = (TERMS == 3) ? 2 * A_TB : A_TB;
    constexpr int STG  = (TERMS == 3) ? 2 * (A_TB + B_TB) : (A_TB + B_TB);

    const int tid  = threadIdx.x;
    const int wid  = tid >> 5;
    const int lane = tid & 31;
    const int wn = wid * 32;

    const uint32_t sm0 = (uint32_t)__cvta_generic_to_shared(smem);

    const int a_row = (lane & 7) + ((lane >> 3) & 1) * 8;
    const int a_kc  = ((lane >> 4) & 1);        // k-chunk (16B) within k16
    const int b_row = (lane & 7) + ((lane >> 4) & 1) * 8;
    const int b_kc  = ((lane >> 3) & 1);

    const int nk = K / 32;

    auto load_stage = [&](int s, int k0) {
        const uint32_t st = sm0 + s * STG;
        #pragma unroll
        for (int c = tid; c < 256; c += 128) {        // A: 64 rows x 4 chunks
            const int row = c >> 2, ch = c & 3;
            const uint32_t sa = st + swz(row, ch);
            const long long g = aBase + (long long)row * K + k0 + ch * 8;
            CPA(sa, Ah + g);
            if (TERMS == 3) CPA(sa + A_TB, Al + g);
        }
        #pragma unroll
        for (int c = tid; c < 512; c += 128) {        // B: 128 rows x 4 chunks
            const int row = c >> 2, ch = c & 3;
            const uint32_t sb = st + BOFF + swz(row, ch);
            const long long g = bBase + (long long)row * K + k0 + ch * 8;
            CPA(sb, Bh + g);
            if (TERMS == 3) CPA(sb + B_TB, Bl + g);
        }
    };

    #pragma unroll
    for (int s = 0; s < NSTG - 1; s++) {
        load_stage(s, s * 32);
        CP_COMMIT();
    }

    for (int kt = 0; kt < nk; kt++) {
        cp_wait<NSTG - 2>();
        __syncthreads();

        const int knext = kt + NSTG - 1;
        if (knext < nk)
            load_stage(knext % NSTG, knext * 32);     // overlaps compute
        CP_COMMIT();

        const uint32_t st  = sm0 + (kt % NSTG) * STG;
        const uint32_t stA = st, stB = st + BOFF;

        #pragma unroll
        for (int ks = 0; ks < 2; ks++) {
            const int kc = ks * 2;                    // 16B chunk base of k16
            uint32_t ah[4][4], al[4][4];
            #pragma unroll
            for (int i = 0; i < 4; i++) {
                const int row = i * 16 + a_row;
                const uint32_t off = swz(row, kc + a_kc);
                LDSM4(ah[i][0], ah[i][1], ah[i][2], ah[i][3], stA + off);
                if (TERMS == 3)
                    LDSM4(al[i][0], al[i][1], al[i][2], al[i][3], stA + A_TB + off);
            }
            #pragma unroll
            for (int j2 = 0; j2 < 2; j2++) {
                uint32_t bh[4], bl[4];
                const int row = wn + j2 * 16 + b_row;
                const uint32_t off = swz(row, kc + b_kc);
                LDSM4(bh[0], bh[1], bh[2], bh[3], stB + off);
                if (TERMS == 3)
                    LDSM4(bl[0], bl[1], bl[2], bl[3], stB + B_TB + off);
                #pragma unroll
                for (int i = 0; i < 4; i++) {
                    if (FP16) {
                        MMA_FP16(acc[i][2*j2],   ah[i], bh[0], bh[1]);
                        MMA_FP16(acc[i][2*j2+1], ah[i], bh[2], bh[3]);
                    } else {
                        MMA_BF16(acc[i][2*j2],   ah[i], bh[0], bh[1]);
                        MMA_BF16(acc[i][2*j2+1], ah[i], bh[2], bh[3]);
                        if (TERMS == 3) {
                            MMA_BF16(acc[i][2*j2],   ah[i], bl[0], bl[1]);
                            MMA_BF16(acc[i][2*j2],   al[i], bh[0], bh[1]);
                            MMA_BF16(acc[i][2*j2+1], ah[i], bl[2], bl[3]);
                            MMA_BF16(acc[i][2*j2+1], al[i], bh[2], bh[3]);
                        }
                    }
                }
            }
        }
    }
}

constexpr int SMEM_G3 = 2 * 2 * (64 * 64 + 128 * 64);   // 49152 (TERMS=3, NST=2)
constexpr int SMEM_F1 = 4 * (64 * 64 + 128 * 64);       // 49152 (fp16, NST=4)

// ---------------------------------------------------------------------------
// Merged projection kernel: grid (4, 384). LONG BLOCKS FIRST:
//   y < 128 : T = dec @ M (TERMS=3 bf16, NSTG=2), split-bf16 epilogue
//   y >= 128: V^T = enc16 @ WvT16^T (fp16 single-term, NSTG=4)
// ---------------------------------------------------------------------------
__global__ void __launch_bounds__(128, 4)
proj2_kernel(const bf16* dec_h, const bf16* dec_l,
             const bf16* mt_h, const bf16* mt_l,
             const __half* enc16, const __half* wvT16,
             bf16* t_h, bf16* t_l, __half* vt)
{
    extern __shared__ __align__(128) char smem[];
    const int y = blockIdx.y;
    const int n0 = blockIdx.x * 128;
    const int wid = threadIdx.x >> 5, lane = threadIdx.x & 31;

    float acc[4][4][4];
    #pragma unroll
    for (int i = 0; i < 4; i++)
        #pragma unroll
        for (int j = 0; j < 4; j++)
            #pragma unroll
            for (int e = 0; e < 4; e++) acc[i][j][e] = 0.f;

    if (y < 128) {
        // ---- T projection (3-term bf16) — LONG blocks, scheduled first ----
        const int arow0 = y * 64;
        gemm_mainloop<3, false, 2>(
            (const uint16_t*)dec_h, (const uint16_t*)dec_l,
            (const uint16_t*)mt_h, (const uint16_t*)mt_l,
            (long long)arow0 * DIN, (long long)n0 * DIN, DIN, acc, smem);

        const int rr0 = arow0 + (lane >> 2);
        const int cc0 = n0 + wid * 32 + (lane & 3) * 2;
        #pragma unroll
        for (int i = 0; i < 4; i++) {
            #pragma unroll
            for (int j = 0; j < 4; j++) {
                const float* a = acc[i][j];
                const int r0 = rr0 + i * 16;
                const int c  = cc0 + j * 8;
                bf16 h0,l0,h1,l1,h2,l2,h3,l3;
                split2(a[0],h0,l0); split2(a[1],h1,l1);
                split2(a[2],h2,l2); split2(a[3],h3,l3);
                const size_t i0 = (size_t)r0 * DIN + c;
                const size_t i1 = (size_t)(r0 + 8) * DIN + c;
                *(__nv_bfloat162*)(t_h + i0) = __nv_bfloat162(h0, h1);
                *(__nv_bfloat162*)(t_l + i0) = __nv_bfloat162(l0, l1);
                *(__nv_bfloat162*)(t_h + i1) = __nv_bfloat162(h2, h3);
                *(__nv_bfloat162*)(t_l + i1) = __nv_bfloat162(l2, l3);
            }
        }
    } else {
        // ---- V projection (fp16 single-term) ----
        const int arow0 = (y - 128) * 64;
        gemm_mainloop<1, true, 4>(
            (const uint16_t*)enc16, nullptr,
            (const uint16_t*)wvT16, nullptr,
            (long long)arow0 * DIN, (long long)n0 * DIN, DIN, acc, smem);

        const int rr0 = arow0 + (lane >> 2);
        const int cc0 = n0 + wid * 32 + (lane & 3) * 2;
        #pragma unroll
        for (int i = 0; i < 4; i++) {
            #pragma unroll
            for (int j = 0; j < 4; j++) {
                const float* a = acc[i][j];
                const int r0 = rr0 + i * 16;
                const int c  = cc0 + j * 8;
                #pragma unroll
                for (int e = 0; e < 4; e++) {
                    const int rr = r0 + (e >> 1) * 8;        // enc row
                    const int cn = c + (e & 1);              // unit
                    const size_t idx = (size_t)(rr >> 11) * ((size_t)UNITS * SENC)
                                     + (size_t)cn * SENC + (rr & 2047);
                    vt[idx] = __float2half(a[e]);
                }
            }
        }
    }
}

// ---------------------------------------------------------------------------
// Scores: S[b] = T[b] @ enc[b]^T, BM=64, BN=128, K=512, TERMS=3, fp32 out.
// grid = (16, 16, 8). S written with streaming hint (read once by softmax).
// ---------------------------------------------------------------------------
__global__ void __launch_bounds__(128, 4)
scores_kernel(const bf16* t_h, const bf16* t_l,
              const bf16* enc_h, const bf16* enc_l, float* __restrict__ S)
{
    extern __shared__ __align__(128) char smem[];
    const int z = blockIdx.z;
    const int m0 = blockIdx.y * 64;
    const int n0 = blockIdx.x * 128;

    float acc[4][4][4];
    #pragma unroll
    for (int i = 0; i < 4; i++)
        #pragma unroll
        for (int j = 0; j < 4; j++)
            #pragma unroll
            for (int e = 0; e < 4; e++) acc[i][j][e] = 0.f;

    gemm_mainloop<3, false, 2>(
        (const uint16_t*)t_h, (const uint16_t*)t_l,
        (const uint16_t*)enc_h, (const uint16_t*)enc_l,
        ((long long)z * SDEC + m0) * DIN,
        ((long long)z * SENC + n0) * DIN, DIN, acc, smem);

    const int wid = threadIdx.x >> 5, lane = threadIdx.x & 31;
    const int rr0 = m0 + (lane >> 2);
    const int cc0 = n0 + wid * 32 + (lane & 3) * 2;
    float* Sb = S + (long long)z * SDEC * SENC;

    #pragma unroll
    for (int i = 0; i < 4; i++) {
        #pragma unroll
        for (int j = 0; j < 4; j++) {
            const float* a = acc[i][j];
            const int r0 = rr0 + i * 16;
            const int c  = cc0 + j * 8;
            __stcs((float2*)(Sb + (long long)r0 * SENC + c),
                   make_float2(a[0], a[1]));
            __stcs((float2*)(Sb + (long long)(r0 + 8) * SENC + c),
                   make_float2(a[2], a[3]));
        }
    }
}

// ---------------------------------------------------------------------------
// PV: out[b] = P[b] @ V[b]. BM=64, BN=128, K=2048, fp16, NSTG=4. grid (4,16,8)
// ---------------------------------------------------------------------------
__global__ void __launch_bounds__(128, 4)
pv_kernel(const __half* P, const __half* VT, float* __restrict__ O)
{
    extern __shared__ __align__(128) char smem[];
    const int z = blockIdx.z;
    const int m0 = blockIdx.y * 64;
    const int n0 = blockIdx.x * 128;

    float acc[4][4][4];
    #pragma unroll
    for (int i = 0; i < 4; i++)
        #pragma unroll
        for (int j = 0; j < 4; j++)
            #pragma unroll
            for (int e = 0; e < 4; e++) acc[i][j][e] = 0.f;

    gemm_mainloop<1, true, 4>(
        (const uint16_t*)P, nullptr, (const uint16_t*)VT, nullptr,
        ((long long)z * SDEC + m0) * SENC,
        ((long long)z * UNITS + n0) * SENC, SENC, acc, smem);

    const int wid = threadIdx.x >> 5, lane = threadIdx.x & 31;
    const int rr0 = m0 + (lane >> 2);
    const int cc0 = n0 + wid * 32 + (lane & 3) * 2;
    float* Ob = O + (long long)z * SDEC * UNITS;

    #pragma unroll
    for (int i = 0; i < 4; i++) {
        #pragma unroll
        for (int j = 0; j < 4; j++) {
            const float* a = acc[i][j];
            const int r0 = rr0 + i * 16;
            const int c  = cc0 + j * 8;
            *(float2*)(Ob + (long long)r0 * UNITS + c)       = make_float2(a[0], a[1]);
            *(float2*)(Ob + (long long)(r0 + 8) * UNITS + c) = make_float2(a[2], a[3]);
        }
    }
}

// ---------------------------------------------------------------------------
// Merged prep kernel (256 threads). MGEMM BLOCKS FIRST (longest):
//  blocks [0,256):     MT = Wk*Wq^T (fp32 exact) -> split bf16 (32x32 tile)
//  blocks [256,1280):  dec -> bf16 hi/lo           (4x ILP)
//  blocks [1280,3328): enc -> bf16 hi/lo + fp16    (4x ILP)
//  blocks [3328,3584): Wv  -> Wv^T fp16            (4x ILP)
// ---------------------------------------------------------------------------
__global__ void __launch_bounds__(256)
prep_kernel(const float4* __restrict__ dec, const float4* __restrict__ enc,
            const float* __restrict__ Wv,
            const float* __restrict__ Wk, const float* __restrict__ Wq,
            __nv_bfloat162* __restrict__ dh, __nv_bfloat162* __restrict__ dl,
            __nv_bfloat162* __restrict__ eh, __nv_bfloat162* __restrict__ el,
            __half2* __restrict__ e16, __half* __restrict__ v16,
            bf16* __restrict__ mh, bf16* __restrict__ ml)
{
    const int b = blockIdx.x;
    if (b < 256) {
        // ---- MT = Wk * Wq^T (exact fp32 SIMT) ----
        __shared__ float As[16][36];
        __shared__ float Bs[16][36];
        const int e0 = (b >> 4) * 32, d0 = (b & 15) * 32;
        const int tid = threadIdx.x;
        const int ty = tid >> 4, tx = tid & 15;

        float c00 = 0.f, c01 = 0.f, c10 = 0.f, c11 = 0.f;

        for (int u0 = 0; u0 < 512; u0 += 16) {
            {
                const int t = tid & 127;
                const int row = t >> 2, col = (t & 3) * 4;
                if (tid < 128) {
                    float4 a = *(const float4*)(Wk + (size_t)(e0 + row) * 512 + u0 + col);
                    As[col+0][row] = a.x; As[col+1][row] = a.y;
                    As[col+2][row] = a.z; As[col+3][row] = a.w;
                } else {
                    float4 bb = *(const float4*)(Wq + (size_t)(d0 + row) * 512 + u0 + col);
                    Bs[col+0][row] = bb.x; Bs[col+1][row] = bb.y;
                    Bs[col+2][row] = bb.z; Bs[col+3][row] = bb.w;
                }
            }
            __syncthreads();
            #pragma unroll
            for (int k = 0; k < 16; k++) {
                float a0 = As[k][ty*2], a1 = As[k][ty*2+1];
                float b0 = Bs[k][tx*2], b1 = Bs[k][tx*2+1];
                c00 += a0*b0; c01 += a0*b1; c10 += a1*b0; c11 += a1*b1;
            }
            __syncthreads();
        }
        bf16 h, l;
        size_t i0 = (size_t)(e0 + ty*2) * 512 + d0 + tx*2;
        size_t i1 = i0 + 512;
        split2(c00, h, l); mh[i0]   = h; ml[i0]   = l;
        split2(c01, h, l); mh[i0+1] = h; ml[i0+1] = l;
        split2(c10, h, l); mh[i1]   = h; ml[i1]   = l;
        split2(c11, h, l); mh[i1+1] = h; ml[i1+1] = l;
    } else if (b < 1280) {
        const int base = (b - 256) * 1024;
        float4 v[4];
        #pragma unroll
        for (int it = 0; it < 4; it++)
            v[it] = dec[base + it * 256 + threadIdx.x];
        #pragma unroll
        for (int it = 0; it < 4; it++) {
            const int i = base + it * 256 + threadIdx.x;
            bf16 h0,l0,h1,l1,h2,l2,h3,l3;
            split2(v[it].x,h0,l0); split2(v[it].y,h1,l1);
            split2(v[it].z,h2,l2); split2(v[it].w,h3,l3);
            dh[2*i]   = __nv_bfloat162(h0,h1);
            dh[2*i+1] = __nv_bfloat162(h2,h3);
            dl[2*i]   = __nv_bfloat162(l0,l1);
            dl[2*i+1] = __nv_bfloat162(l2,l3);
        }
    } else if (b < 3328) {
        const int base = (b - 1280) * 1024;
        float4 v[4];
        #pragma unroll
        for (int it = 0; it < 4; it++)
            v[it] = enc[base + it * 256 + threadIdx.x];
        #pragma unroll
        for (int it = 0; it < 4; it++) {
            const int i = base + it * 256 + threadIdx.x;
            bf16 h0,l0,h1,l1,h2,l2,h3,l3;
            split2(v[it].x,h0,l0); split2(v[it].y,h1,l1);
            split2(v[it].z,h2,l2); split2(v[it].w,h3,l3);
            eh[2*i]   = __nv_bfloat162(h0,h1);
            eh[2*i+1] = __nv_bfloat162(h2,h3);
            el[2*i]   = __nv_bfloat162(l0,l1);
            el[2*i+1] = __nv_bfloat162(l2,l3);
            e16[2*i]   = __floats2half2_rn(v[it].x, v[it].y);
            e16[2*i+1] = __floats2half2_rn(v[it].z, v[it].w);
        }
    } else {
        const int base = (b - 3328) * 1024;               // [0, 262144)
        float w[4];
        #pragma unroll
        for (int it = 0; it < 4; it++)
            w[it] = Wv[base + it * 256 + threadIdx.x];
        #pragma unroll
        for (int it = 0; it < 4; it++) {
            const int idx = base + it * 256 + threadIdx.x;
            const int k = idx >> 9, n = idx & 511;
            v16[n * 512 + k] = __float2half(w[it]);
        }
    }
}

// ---------------------------------------------------------------------------
// Row softmax over 2048 fp32 scores -> fp16 probabilities (streaming S reads)
// ---------------------------------------------------------------------------
__inline__ __device__ float warpMax(float v) {
    #pragma unroll
    for (int o = 16; o; o >>= 1) v = fmaxf(v, __shfl_xor_sync(0xffffffffu, v, o));
    return v;
}
__inline__ __device__ float warpSum(float v) {
    #pragma unroll
    for (int o = 16; o; o >>= 1) v += __shfl_xor_sync(0xffffffffu, v, o);
    return v;
}

__global__ void __launch_bounds__(256)
softmax_h(const float* __restrict__ S, __half* __restrict__ P)
{
    const long long row = blockIdx.x;
    const float4* p = (const float4*)(S + row * (long long)SENC);
    const int tid = threadIdx.x, lane = tid & 31, wid = tid >> 5;

    float4 v0 = __ldcs(&p[tid]);
    float4 v1 = __ldcs(&p[tid + 256]);

    float m = fmaxf(fmaxf(fmaxf(v0.x, v0.y), fmaxf(v0.z, v0.w)),
                    fmaxf(fmaxf(v1.x, v1.y), fmaxf(v1.z, v1.w)));
    __shared__ float smax[8], ssum[8];
    m = warpMax(m);
    if (lane == 0) smax[wid] = m;
    __syncthreads();
    float bm = smax[0];
    #pragma unroll
    for (int i = 1; i < 8; i++) bm = fmaxf(bm, smax[i]);

    v0.x = __expf(v0.x - bm); v0.y = __expf(v0.y - bm);
    v0.z = __expf(v0.z - bm); v0.w = __expf(v0.w - bm);
    v1.x = __expf(v1.x - bm); v1.y = __expf(v1.y - bm);
    v1.z = __expf(v1.z - bm); v1.w = __expf(v1.w - bm);

    float s = (v0.x + v0.y + v0.z + v0.w) + (v1.x + v1.y + v1.z + v1.w);
    s = warpSum(s);
    if (lane == 0) ssum[wid] = s;
    __syncthreads();
    float bs = 0.f;
    #pragma unroll
    for (int i = 0; i < 8; i++) bs += ssum[i];
    const float inv = 1.0f / bs;

    __half2* ph = (__half2*)(P + row * (long long)SENC);
    ph[2*tid]         = __floats2half2_rn(v0.x * inv, v0.y * inv);
    ph[2*tid+1]       = __floats2half2_rn(v0.z * inv, v0.w * inv);
    ph[512 + 2*tid]   = __floats2half2_rn(v1.x * inv, v1.y * inv);
    ph[512 + 2*tid+1] = __floats2half2_rn(v1.z * inv, v1.w * inv);
}

// ---------------------------------------------------------------------------
extern "C" void kernel_launch(void* const* d_in, const int* in_sizes, int n_in,
                              void* d_out, int out_size)
{
    const float* enc = (const float*)d_in[0];
    const float* dec = (const float*)d_in[1];
    const float* Wq  = (const float*)d_in[2];
    const float* Wk  = (const float*)d_in[3];
    const float* Wv  = (const float*)d_in[4];
    float* out = (float*)d_out;

    bf16 *dec_h,*dec_l,*enc_h,*enc_l,*mt_h,*mt_l,*t_h,*t_l;
    __half *enc16, *wvT16, *vt16, *p16;
    float *s;
    cudaGetSymbolAddress((void**)&dec_h, g_dec_h);
    cudaGetSymbolAddress((void**)&dec_l, g_dec_l);
    cudaGetSymbolAddress((void**)&enc_h, g_enc_h);
    cudaGetSymbolAddress((void**)&enc_l, g_enc_l);
    cudaGetSymbolAddress((void**)&enc16, g_enc16);
    cudaGetSymbolAddress((void**)&wvT16, g_wvT16);
    cudaGetSymbolAddress((void**)&mt_h, g_mt_h);
    cudaGetSymbolAddress((void**)&mt_l, g_mt_l);
    cudaGetSymbolAddress((void**)&t_h, g_t_h);
    cudaGetSymbolAddress((void**)&t_l, g_t_l);
    cudaGetSymbolAddress((void**)&vt16, g_vt16);
    cudaGetSymbolAddress((void**)&p16, g_p16);
    cudaGetSymbolAddress((void**)&s, g_s);

    cudaFuncSetAttribute(proj2_kernel,  cudaFuncAttributeMaxDynamicSharedMemorySize, SMEM_F1);
    cudaFuncSetAttribute(scores_kernel, cudaFuncAttributeMaxDynamicSharedMemorySize, SMEM_G3);
    cudaFuncSetAttribute(pv_kernel,     cudaFuncAttributeMaxDynamicSharedMemorySize, SMEM_F1);

    // 1. all prep in one launch (mgemm blocks FIRST so they overlap splits)
    prep_kernel<<<3584, 256>>>(
        (const float4*)dec, (const float4*)enc, Wv, Wk, Wq,
        (__nv_bfloat162*)dec_h, (__nv_bfloat162*)dec_l,
        (__nv_bfloat162*)enc_h, (__nv_bfloat162*)enc_l,
        (__half2*)enc16, wvT16, mt_h, mt_l);

    // 2. merged projections: T (3-term, long, first) + V^T (fp16)
    proj2_kernel<<<dim3(4, 384), 128, SMEM_F1>>>(
        dec_h, dec_l, mt_h, mt_l, enc16, wvT16, t_h, t_l, vt16);

    // 3. scores S = T @ enc^T (batched)
    scores_kernel<<<dim3(16, 16, 8), 128, SMEM_G3>>>(t_h, t_l, enc_h, enc_l, s);

    // 4. softmax -> fp16 P
    softmax_h<<<NB * SDEC, 256>>>(s, p16);

    // 5. out = P @ V
    pv_kernel<<<dim3(4, 16, 8), 128, SMEM_F1>>>(p16, vt16, out);
}